// round 7
// baseline (speedup 1.0000x reference)
#include <cuda_runtime.h>

typedef unsigned long long ull;

// ---------------- scratch (device globals; no allocation allowed) ----------------
static __device__ __align__(16) float g_a1[64*32*128*128];          // enc1 out
static __device__ __align__(16) float g_a2[64*64*64*64];            // enc2 out
static __device__ __align__(16) float g_q [64*16*64*64];            // quantized (decoder input)
static __device__ __align__(16) float g_d1[64*64*128*128];          // dec1 out
static __device__ __align__(16) float g_d2[64*32*256*256];          // dec2 out
static __device__ float g_pvq [1024];                               // per-block VQ sq-sum
static __device__ float g_pmse[2048];                               // per-block recon sq-sum

// ---------------- f32x2 helpers ----------------
__device__ __forceinline__ ull pk2(float lo, float hi) {
    ull r;
    asm("mov.b64 %0, {%1, %2};" : "=l"(r)
        : "r"(__float_as_uint(lo)), "r"(__float_as_uint(hi)));
    return r;
}
__device__ __forceinline__ float2 upk2(ull p) {
    unsigned int a, b;
    asm("mov.b64 {%0, %1}, %2;" : "=r"(a), "=r"(b) : "l"(p));
    return make_float2(__uint_as_float(a), __uint_as_float(b));
}
__device__ __forceinline__ ull ffma2(ull a, ull b, ull c) {
    ull d;
    asm("fma.rn.f32x2 %0, %1, %2, %3;" : "=l"(d) : "l"(a), "l"(b), "l"(c));
    return d;
}
__device__ __forceinline__ float4 z4() { return make_float4(0.f, 0.f, 0.f, 0.f); }

// ---------------- reduction helper ----------------
__device__ __forceinline__ float block_sum(float v, float* sred) {
    int lane = threadIdx.x & 31, w = threadIdx.x >> 5;
    #pragma unroll
    for (int o = 16; o > 0; o >>= 1) v += __shfl_down_sync(0xffffffffu, v, o);
    if (lane == 0) sred[w] = v;
    __syncthreads();
    if (w == 0) {
        v = (lane < (int)(blockDim.x >> 5)) ? sred[lane] : 0.f;
        #pragma unroll
        for (int o = 16; o > 0; o >>= 1) v += __shfl_down_sync(0xffffffffu, v, o);
    }
    return v;  // valid in thread 0
}

#define FMA4(ACC, J, V, W4)                         \
    do {                                            \
        ACC[4*(J)+0] = fmaf(V, (W4).x, ACC[4*(J)+0]); \
        ACC[4*(J)+1] = fmaf(V, (W4).y, ACC[4*(J)+1]); \
        ACC[4*(J)+2] = fmaf(V, (W4).z, ACC[4*(J)+2]); \
        ACC[4*(J)+3] = fmaf(V, (W4).w, ACC[4*(J)+3]); \
    } while (0)

// transposed-conv tap: pair weights layout wq.x=(w1,w2) wq.y=(0,w0)
template <int C>
__device__ __forceinline__ void ctap(float4 f, float v4, const ull* wp, ull* acc) {
    ull d0 = pk2(f.x, f.x), d1 = pk2(f.y, f.y), d2 = pk2(f.z, f.z), d3 = pk2(f.w, f.w);
    ull o0 = pk2(f.x, f.y), o1 = pk2(f.y, f.z), o2 = pk2(f.z, f.w), o3 = pk2(f.w, v4);
    #pragma unroll
    for (int oc = 0; oc < C; oc++) {
        ulonglong2 wq = *(const ulonglong2*)(wp + oc * 2);
        acc[oc*4+0] = ffma2(d0, wq.x, ffma2(o0, wq.y, acc[oc*4+0]));
        acc[oc*4+1] = ffma2(d1, wq.x, ffma2(o1, wq.y, acc[oc*4+1]));
        acc[oc*4+2] = ffma2(d2, wq.x, ffma2(o2, wq.y, acc[oc*4+2]));
        acc[oc*4+3] = ffma2(d3, wq.x, ffma2(o3, wq.y, acc[oc*4+3]));
    }
}

// ---------------- enc1: conv 3->32, k3 s2 p1, ReLU (zero-fill, batched loads) --------
__global__ void __launch_bounds__(256) k_enc1(const float* __restrict__ x,
                                              const float* __restrict__ w,
                                              const float* __restrict__ bias) {
    __shared__ __align__(16) float s_w[27 * 32];
    __shared__ float s_b[32];
    for (int i = threadIdx.x; i < 27 * 32; i += 256) {
        int oc = i & 31, t = i >> 5;
        s_w[i] = w[oc * 27 + t];
    }
    if (threadIdx.x < 32) s_b[threadIdx.x] = bias[threadIdx.x];
    __syncthreads();

    int tid = blockIdx.x * 256 + threadIdx.x;
    int ow = tid & 127, oh = (tid >> 7) & 127, b = tid >> 14;

    float acc[32];
    #pragma unroll
    for (int oc = 0; oc < 32; oc++) acc[oc] = s_b[oc];

    float v[27];
    #pragma unroll
    for (int ic = 0; ic < 3; ic++) {
        const float* xp = x + (size_t)(b * 3 + ic) * 65536;
        #pragma unroll
        for (int kh = 0; kh < 3; kh++) {
            int ih = oh * 2 + kh - 1;
            bool okh = (unsigned)ih < 256u;
            #pragma unroll
            for (int kw = 0; kw < 3; kw++) {
                int iw = ow * 2 + kw - 1;
                bool ok = okh && ((unsigned)iw < 256u);
                v[ic * 9 + kh * 3 + kw] = ok ? xp[ih * 256 + iw] : 0.f;
            }
        }
    }
    #pragma unroll
    for (int t = 0; t < 27; t++) {
        const float4* wp = (const float4*)&s_w[t * 32];
        #pragma unroll
        for (int j = 0; j < 8; j++) { float4 w4 = wp[j]; FMA4(acc, j, v[t], w4); }
    }
    float* op = g_a1 + (size_t)b * 32 * 16384 + oh * 128 + ow;
    #pragma unroll
    for (int oc = 0; oc < 32; oc++) op[oc * 16384] = fmaxf(acc[oc], 0.f);
}

// ---------------- enc2: conv 32->64, k3 s2 p1, ReLU (P=8, C=8, f32x2, zero-fill) -----
// block: chunk(8) x ocg(8) x row(4) = 256. grid: 64b * 16 rowgroups = 1024.
__global__ void __launch_bounds__(256) k_enc2(const float* __restrict__ w,
                                              const float* __restrict__ bias) {
    extern __shared__ __align__(16) ull smu[];
    ull* s_w = smu;                // 18432: [kh][ic][kw][oc] dup pairs
    ull* s_bd = smu + 18432;       // 64
    for (int i = threadIdx.x; i < 18432; i += 256) {
        int oc = i & 63; int t = i >> 6; int kw = t % 3; t /= 3; int ic = t & 31; int kh = t >> 5;
        float wv = w[((oc * 32 + ic) * 3 + kh) * 3 + kw];
        s_w[i] = pk2(wv, wv);
    }
    if (threadIdx.x < 64) { float bv = bias[threadIdx.x]; s_bd[threadIdx.x] = pk2(bv, bv); }
    __syncthreads();

    int tx = threadIdx.x;
    int chunk = tx & 7, ocg = (tx >> 3) & 7, r = tx >> 6;
    int b = blockIdx.x >> 4, rg = blockIdx.x & 15;
    int oh = rg * 4 + r;
    int ocb = ocg * 8;
    int ow0 = chunk * 8;

    ull acc[32];
    #pragma unroll
    for (int oc = 0; oc < 8; oc++) {
        ull bp = s_bd[ocb + oc];
        acc[oc*4+0] = bp; acc[oc*4+1] = bp; acc[oc*4+2] = bp; acc[oc*4+3] = bp;
    }

    #pragma unroll 1
    for (int ic = 0; ic < 32; ic++) {
        const float* plane = g_a1 + (size_t)(b * 32 + ic) * 16384;
        #pragma unroll
        for (int kh = 0; kh < 3; kh++) {
            int ih = 2 * oh + kh - 1;
            bool okh = (unsigned)ih < 128u;
            const float* row = plane + ih * 128 + chunk * 16;
            float vm1 = (okh && chunk != 0) ? row[-1] : 0.f;
            float4 g0 = okh ? *(const float4*)row        : z4();
            float4 g1 = okh ? *(const float4*)(row + 4)  : z4();
            float4 g2 = okh ? *(const float4*)(row + 8)  : z4();
            float4 g3 = okh ? *(const float4*)(row + 12) : z4();
            ull P00 = pk2(vm1,  g0.y), P01 = pk2(g0.w, g1.y), P02 = pk2(g1.w, g2.y), P03 = pk2(g2.w, g3.y);
            ull P10 = pk2(g0.x, g0.z), P11 = pk2(g1.x, g1.z), P12 = pk2(g2.x, g2.z), P13 = pk2(g3.x, g3.z);
            ull P20 = pk2(g0.y, g0.w), P21 = pk2(g1.y, g1.w), P22 = pk2(g2.y, g2.w), P23 = pk2(g3.y, g3.w);
            const ull* wp0 = s_w + ((kh * 32 + ic) * 3 + 0) * 64 + ocb;
            const ull* wp1 = s_w + ((kh * 32 + ic) * 3 + 1) * 64 + ocb;
            const ull* wp2 = s_w + ((kh * 32 + ic) * 3 + 2) * 64 + ocb;
            #pragma unroll
            for (int oc = 0; oc < 8; oc++) {
                ull w0 = wp0[oc], w1 = wp1[oc], w2 = wp2[oc];
                acc[oc*4+0] = ffma2(P00, w0, ffma2(P10, w1, ffma2(P20, w2, acc[oc*4+0])));
                acc[oc*4+1] = ffma2(P01, w0, ffma2(P11, w1, ffma2(P21, w2, acc[oc*4+1])));
                acc[oc*4+2] = ffma2(P02, w0, ffma2(P12, w1, ffma2(P22, w2, acc[oc*4+2])));
                acc[oc*4+3] = ffma2(P03, w0, ffma2(P13, w1, ffma2(P23, w2, acc[oc*4+3])));
            }
        }
    }

    float* op = g_a2 + ((size_t)(b * 64 + ocb) * 64 + oh) * 64 + ow0;
    #pragma unroll
    for (int oc = 0; oc < 8; oc++) {
        float2 p0 = upk2(acc[oc*4+0]), p1 = upk2(acc[oc*4+1]);
        float2 p2 = upk2(acc[oc*4+2]), p3 = upk2(acc[oc*4+3]);
        float4 lo = make_float4(fmaxf(p0.x,0.f), fmaxf(p0.y,0.f), fmaxf(p1.x,0.f), fmaxf(p1.y,0.f));
        float4 hi = make_float4(fmaxf(p2.x,0.f), fmaxf(p2.y,0.f), fmaxf(p3.x,0.f), fmaxf(p3.y,0.f));
        *(float4*)(op + (size_t)oc * 4096) = lo;
        *(float4*)(op + (size_t)oc * 4096 + 4) = hi;
    }
}

// ---------------- enc3 (1x1, 64->16) + VQ + q-loss (unchanged) ----------------
__global__ void __launch_bounds__(256) k_enc3_vq(const float* __restrict__ w3,
                                                 const float* __restrict__ b3,
                                                 const float* __restrict__ cb) {
    __shared__ __align__(16) float s_w[64 * 16];
    __shared__ float s_b[16];
    __shared__ __align__(16) float s_cb[512 * 16];
    __shared__ float s_cn[512];
    __shared__ float sred[32];

    for (int i = threadIdx.x; i < 1024; i += 256) {
        int d = i & 15, ic = i >> 4;
        s_w[i] = w3[d * 64 + ic];
    }
    if (threadIdx.x < 16) s_b[threadIdx.x] = b3[threadIdx.x];
    for (int i = threadIdx.x; i < 8192; i += 256) s_cb[i] = cb[i];
    __syncthreads();
    for (int j = threadIdx.x; j < 512; j += 256) {
        float s = 0.f;
        #pragma unroll
        for (int d = 0; d < 16; d++) { float c = s_cb[j * 16 + d]; s = fmaf(c, c, s); }
        s_cn[j] = s;
    }
    __syncthreads();

    int tid = blockIdx.x * 256 + threadIdx.x;
    int p = tid & 4095, b = tid >> 12;

    float z[16];
    #pragma unroll
    for (int d = 0; d < 16; d++) z[d] = s_b[d];
    const float* ap = g_a2 + (size_t)b * 64 * 4096 + p;
    #pragma unroll 8
    for (int ic = 0; ic < 64; ic++) {
        float v = ap[ic * 4096];
        const float4* wp = (const float4*)&s_w[ic * 16];
        #pragma unroll
        for (int j = 0; j < 4; j++) { float4 w4 = wp[j]; FMA4(z, j, v, w4); }
    }

    int best = 0; float bd = 3.4e38f;
    for (int j = 0; j < 512; j++) {
        const float4* cp = (const float4*)&s_cb[j * 16];
        float dot = 0.f;
        #pragma unroll
        for (int q4 = 0; q4 < 4; q4++) {
            float4 c4 = cp[q4];
            dot = fmaf(z[4*q4+0], c4.x, dot);
            dot = fmaf(z[4*q4+1], c4.y, dot);
            dot = fmaf(z[4*q4+2], c4.z, dot);
            dot = fmaf(z[4*q4+3], c4.w, dot);
        }
        float dist = s_cn[j] - 2.f * dot;
        if (dist < bd) { bd = dist; best = j; }
    }

    float sq = 0.f;
    float* qp = g_q + (size_t)b * 16 * 4096 + p;
    #pragma unroll
    for (int d = 0; d < 16; d++) {
        float qv = s_cb[best * 16 + d];
        float df = qv - z[d];
        sq = fmaf(df, df, sq);
        qp[d * 4096] = qv;
    }
    float bs = block_sum(sq, sred);
    if (threadIdx.x == 0) g_pvq[blockIdx.x] = bs;
}

// ---------------- dec1: convT 16->64 k3 s2 p1 op1, ReLU (prefetch pipeline) ----------
// block: chunk(16) x ocg(4) x r(4) = 256. grid: 64b * 2ph * 16rg = 2048.
__global__ void __launch_bounds__(256) k_dec1(const float* __restrict__ w,
                                              const float* __restrict__ bias) {
    extern __shared__ __align__(16) ull smu[];
    ull* s_w = smu;               // 6144: [kh][ic][oc] -> {(w1,w2),(0,w0)}
    ull* s_bd = smu + 6144;       // 64
    for (int i = threadIdx.x; i < 6144; i += 256) {
        int h = i & 1; int t = i >> 1; int oc = t & 63; int t2 = t >> 6; int ic = t2 & 15; int kh = t2 >> 4;
        const float* wb = w + ((ic * 64 + oc) * 3 + kh) * 3;   // dec_w1 [16][64][3][3]
        s_w[i] = h ? pk2(0.f, wb[0]) : pk2(wb[1], wb[2]);
    }
    if (threadIdx.x < 64) { float bv = bias[threadIdx.x]; s_bd[threadIdx.x] = pk2(bv, bv); }
    __syncthreads();

    int tx = threadIdx.x;
    int chunk = tx & 15, ocg = (tx >> 4) & 3, r = tx >> 6;
    int bi = blockIdx.x;
    int b = bi >> 5; int rem = bi & 31; int ph = rem >> 4; int rg = rem & 15;
    int R = rg * 4 + r;
    int oh = 2 * R + ph;
    int ocb = ocg * 16;
    int ow0 = chunk * 8;

    ull acc[64];
    #pragma unroll
    for (int oc = 0; oc < 16; oc++) {
        ull bp = s_bd[ocb + oc];
        acc[oc*4+0] = bp; acc[oc*4+1] = bp; acc[oc*4+2] = bp; acc[oc*4+3] = bp;
    }

    const float* base = g_q + (size_t)b * 16 * 4096;
    bool edge = (chunk < 15);

    if (ph == 0) {               // single tap kh=1 @ row R
        const float* p0 = base + R * 64 + chunk * 4;
        float4 f = *(const float4*)p0;
        float v4 = edge ? p0[4] : 0.f;
        #pragma unroll 1
        for (int ic = 0; ic < 16; ic++) {
            float4 fc = f; float vc = v4;
            if (ic < 15) {
                const float* nx = p0 + (ic + 1) * 4096;
                f = *(const float4*)nx; v4 = edge ? nx[4] : 0.f;
            }
            ctap<16>(fc, vc, s_w + (((1 * 16 + ic) * 64) + ocb) * 2, acc);
        }
    } else {                     // taps kh=2 @ R, kh=0 @ R+1 (zero beyond edge)
        bool ok = (R + 1 < 64);
        const float* pa = base + R * 64 + chunk * 4;
        const float* pb = base + (R + 1) * 64 + chunk * 4;
        float4 fa = *(const float4*)pa;
        float va = edge ? pa[4] : 0.f;
        float4 fb = ok ? *(const float4*)pb : z4();
        float vb = (ok && edge) ? pb[4] : 0.f;
        #pragma unroll 1
        for (int ic = 0; ic < 16; ic++) {
            float4 fca = fa, fcb = fb; float vca = va, vcb = vb;
            if (ic < 15) {
                const float* na = pa + (ic + 1) * 4096;
                const float* nb = pb + (ic + 1) * 4096;
                fa = *(const float4*)na; va = edge ? na[4] : 0.f;
                fb = ok ? *(const float4*)nb : z4(); vb = (ok && edge) ? nb[4] : 0.f;
            }
            ctap<16>(fca, vca, s_w + (((2 * 16 + ic) * 64) + ocb) * 2, acc);
            ctap<16>(fcb, vcb, s_w + (((0 * 16 + ic) * 64) + ocb) * 2, acc);
        }
    }

    float* op = g_d1 + ((size_t)(b * 64 + ocb) * 128 + oh) * 128 + ow0;
    #pragma unroll
    for (int oc = 0; oc < 16; oc++) {
        float2 p0 = upk2(acc[oc*4+0]), p1 = upk2(acc[oc*4+1]);
        float2 p2 = upk2(acc[oc*4+2]), p3 = upk2(acc[oc*4+3]);
        float4 lo = make_float4(fmaxf(p0.x,0.f), fmaxf(p0.y,0.f), fmaxf(p1.x,0.f), fmaxf(p1.y,0.f));
        float4 hi = make_float4(fmaxf(p2.x,0.f), fmaxf(p2.y,0.f), fmaxf(p3.x,0.f), fmaxf(p3.y,0.f));
        *(float4*)(op + (size_t)oc * 16384) = lo;
        *(float4*)(op + (size_t)oc * 16384 + 4) = hi;
    }
}

// ---------------- dec2: convT 64->32 k3 s2 p1 op1, ReLU (prefetch pipeline) ----------
// block: chunk(32) x ocg(2) x r(4) = 256. grid: 64b * 2ph * 32rg = 4096.
__global__ void __launch_bounds__(256) k_dec2(const float* __restrict__ w,
                                              const float* __restrict__ bias) {
    extern __shared__ __align__(16) ull smu[];
    ull* s_w = smu;                // 12288: [kh][ic][oc] pairs
    ull* s_bd = smu + 12288;       // 32
    for (int i = threadIdx.x; i < 12288; i += 256) {
        int h = i & 1; int t = i >> 1; int oc = t & 31; int t2 = t >> 5; int ic = t2 & 63; int kh = t2 >> 6;
        const float* wb = w + ((ic * 32 + oc) * 3 + kh) * 3;   // dec_w2 [64][32][3][3]
        s_w[i] = h ? pk2(0.f, wb[0]) : pk2(wb[1], wb[2]);
    }
    if (threadIdx.x < 32) { float bv = bias[threadIdx.x]; s_bd[threadIdx.x] = pk2(bv, bv); }
    __syncthreads();

    int tx = threadIdx.x;
    int chunk = tx & 31, ocg = (tx >> 5) & 1, r = tx >> 6;
    int bi = blockIdx.x;
    int b = bi >> 6; int rem = bi & 63; int ph = rem >> 5; int rg = rem & 31;
    int R = rg * 4 + r;
    int oh = 2 * R + ph;
    int ocb = ocg * 16;
    int ow0 = chunk * 8;

    ull acc[64];
    #pragma unroll
    for (int oc = 0; oc < 16; oc++) {
        ull bp = s_bd[ocb + oc];
        acc[oc*4+0] = bp; acc[oc*4+1] = bp; acc[oc*4+2] = bp; acc[oc*4+3] = bp;
    }

    const float* base = g_d1 + (size_t)b * 64 * 16384;
    bool edge = (chunk < 31);

    if (ph == 0) {               // single tap kh=1 @ row R
        const float* p0 = base + R * 128 + chunk * 4;
        float4 f = *(const float4*)p0;
        float v4 = edge ? p0[4] : 0.f;
        #pragma unroll 1
        for (int ic = 0; ic < 64; ic++) {
            float4 fc = f; float vc = v4;
            if (ic < 63) {
                const float* nx = p0 + (ic + 1) * 16384;
                f = *(const float4*)nx; v4 = edge ? nx[4] : 0.f;
            }
            ctap<16>(fc, vc, s_w + (((1 * 64 + ic) * 32) + ocb) * 2, acc);
        }
    } else {                     // taps kh=2 @ R, kh=0 @ R+1
        bool ok = (R + 1 < 128);
        const float* pa = base + R * 128 + chunk * 4;
        const float* pb = base + (R + 1) * 128 + chunk * 4;
        float4 fa = *(const float4*)pa;
        float va = edge ? pa[4] : 0.f;
        float4 fb = ok ? *(const float4*)pb : z4();
        float vb = (ok && edge) ? pb[4] : 0.f;
        #pragma unroll 1
        for (int ic = 0; ic < 64; ic++) {
            float4 fca = fa, fcb = fb; float vca = va, vcb = vb;
            if (ic < 63) {
                const float* na = pa + (ic + 1) * 16384;
                const float* nb = pb + (ic + 1) * 16384;
                fa = *(const float4*)na; va = edge ? na[4] : 0.f;
                fb = ok ? *(const float4*)nb : z4(); vb = (ok && edge) ? nb[4] : 0.f;
            }
            ctap<16>(fca, vca, s_w + (((2 * 64 + ic) * 32) + ocb) * 2, acc);
            ctap<16>(fcb, vcb, s_w + (((0 * 64 + ic) * 32) + ocb) * 2, acc);
        }
    }

    float* op = g_d2 + ((size_t)(b * 32 + ocb) * 256 + oh) * 256 + ow0;
    #pragma unroll
    for (int oc = 0; oc < 16; oc++) {
        float2 p0 = upk2(acc[oc*4+0]), p1 = upk2(acc[oc*4+1]);
        float2 p2 = upk2(acc[oc*4+2]), p3 = upk2(acc[oc*4+3]);
        float4 lo = make_float4(fmaxf(p0.x,0.f), fmaxf(p0.y,0.f), fmaxf(p1.x,0.f), fmaxf(p1.y,0.f));
        float4 hi = make_float4(fmaxf(p2.x,0.f), fmaxf(p2.y,0.f), fmaxf(p3.x,0.f), fmaxf(p3.y,0.f));
        *(float4*)(op + (size_t)oc * 65536) = lo;
        *(float4*)(op + (size_t)oc * 65536 + 4) = hi;
    }
}

// ---------------- dec3: convT 32->3 s1 p1 + fused MSE (zero-fill, batched loads) -----
__global__ void __launch_bounds__(256) k_dec3_mse(const float* __restrict__ w,
                                                  const float* __restrict__ bias,
                                                  const float* __restrict__ x) {
    __shared__ __align__(16) ull s_wd[864];   // [ic][kh][kw][oc] dup pairs
    __shared__ ull s_bd[3];
    __shared__ float sred[32];
    for (int i = threadIdx.x; i < 864; i += 256) {
        int oc = i % 3; int t = i / 3; int kw = t % 3; t /= 3; int kh = t % 3; int ic = t / 3;
        float wv = w[ic * 27 + oc * 9 + (2 - kh) * 3 + (2 - kw)];   // dec_w3 flipped
        s_wd[i] = pk2(wv, wv);
    }
    if (threadIdx.x < 3) { float bv = bias[threadIdx.x]; s_bd[threadIdx.x] = pk2(bv, bv); }
    __syncthreads();

    int tx = threadIdx.x;
    int chunk = tx & 31, r = tx >> 5;
    int b = blockIdx.x >> 5, rg = blockIdx.x & 31;
    int oh = rg * 8 + r;
    int ow0 = chunk * 8;

    ull acc[12];
    #pragma unroll
    for (int oc = 0; oc < 3; oc++) {
        ull bp = s_bd[oc];
        acc[oc*4+0] = bp; acc[oc*4+1] = bp; acc[oc*4+2] = bp; acc[oc*4+3] = bp;
    }

    #pragma unroll 1
    for (int ic = 0; ic < 32; ic++) {
        const float* plane = g_d2 + (size_t)(b * 32 + ic) * 65536;
        #pragma unroll
        for (int kh = 0; kh < 3; kh++) {
            int ih = oh + kh - 1;
            bool okh = (unsigned)ih < 256u;
            const float* row = plane + ih * 256 + ow0;
            float4 f0 = okh ? *(const float4*)row       : z4();
            float4 f1 = okh ? *(const float4*)(row + 4) : z4();
            float vm1 = (okh && chunk != 0)  ? row[-1] : 0.f;
            float v8  = (okh && chunk != 31) ? row[8]  : 0.f;
            ull A0 = pk2(f0.x, f0.y), A1 = pk2(f0.z, f0.w), A2 = pk2(f1.x, f1.y), A3 = pk2(f1.z, f1.w);
            ull O0 = pk2(vm1, f0.x), O1 = pk2(f0.y, f0.z), O2 = pk2(f0.w, f1.x),
                O3 = pk2(f1.y, f1.z), O4 = pk2(f1.w, v8);
            const ull* wp = s_wd + (ic * 3 + kh) * 9;   // [kw][oc]
            #pragma unroll
            for (int oc = 0; oc < 3; oc++) {
                ull w0 = wp[oc], w1 = wp[3 + oc], w2 = wp[6 + oc];
                acc[oc*4+0] = ffma2(O0, w0, ffma2(A0, w1, ffma2(O1, w2, acc[oc*4+0])));
                acc[oc*4+1] = ffma2(O1, w0, ffma2(A1, w1, ffma2(O2, w2, acc[oc*4+1])));
                acc[oc*4+2] = ffma2(O2, w0, ffma2(A2, w1, ffma2(O3, w2, acc[oc*4+2])));
                acc[oc*4+3] = ffma2(O3, w0, ffma2(A3, w1, ffma2(O4, w2, acc[oc*4+3])));
            }
        }
    }

    const float* xp = x + (size_t)b * 3 * 65536 + oh * 256 + ow0;
    float sq = 0.f;
    #pragma unroll
    for (int oc = 0; oc < 3; oc++) {
        float4 x0 = *(const float4*)(xp + (size_t)oc * 65536);
        float4 x1 = *(const float4*)(xp + (size_t)oc * 65536 + 4);
        float2 p0 = upk2(acc[oc*4+0]), p1 = upk2(acc[oc*4+1]);
        float2 p2 = upk2(acc[oc*4+2]), p3 = upk2(acc[oc*4+3]);
        float e;
        e = p0.x - x0.x; sq = fmaf(e, e, sq);
        e = p0.y - x0.y; sq = fmaf(e, e, sq);
        e = p1.x - x0.z; sq = fmaf(e, e, sq);
        e = p1.y - x0.w; sq = fmaf(e, e, sq);
        e = p2.x - x1.x; sq = fmaf(e, e, sq);
        e = p2.y - x1.y; sq = fmaf(e, e, sq);
        e = p3.x - x1.z; sq = fmaf(e, e, sq);
        e = p3.y - x1.w; sq = fmaf(e, e, sq);
    }
    float bs = block_sum(sq, sred);
    if (threadIdx.x == 0) g_pmse[blockIdx.x] = bs;
}

// ---------------- deterministic final reduction ----------------
__global__ void k_final(float* __restrict__ out) {
    __shared__ double sd[256];
    double s1 = 0.0, s2 = 0.0;
    for (int i = threadIdx.x; i < 1024; i += 256) s1 += (double)g_pvq[i];
    for (int i = threadIdx.x; i < 2048; i += 256) s2 += (double)g_pmse[i];
    sd[threadIdx.x] = s1; __syncthreads();
    for (int o = 128; o > 0; o >>= 1) {
        if ((int)threadIdx.x < o) sd[threadIdx.x] += sd[threadIdx.x + o];
        __syncthreads();
    }
    double vq = sd[0]; __syncthreads();
    sd[threadIdx.x] = s2; __syncthreads();
    for (int o = 128; o > 0; o >>= 1) {
        if ((int)threadIdx.x < o) sd[threadIdx.x] += sd[threadIdx.x + o];
        __syncthreads();
    }
    if (threadIdx.x == 0) {
        double mq = vq / 4194304.0;                 // 64*64*64*16
        double mr = sd[0] / 12582912.0;             // 64*3*256*256
        out[0] = (float)(1.25 * mq);
        out[1] = (float)mr;
        out[2] = (float)mr;
    }
}

// ---------------- launch ----------------
extern "C" void kernel_launch(void* const* d_in, const int* in_sizes, int n_in,
                              void* d_out, int out_size) {
    const float* x   = (const float*)d_in[0];
    const float* ew1 = (const float*)d_in[1];
    const float* eb1 = (const float*)d_in[2];
    const float* ew2 = (const float*)d_in[3];
    const float* eb2 = (const float*)d_in[4];
    const float* ew3 = (const float*)d_in[5];
    const float* eb3 = (const float*)d_in[6];
    const float* cb  = (const float*)d_in[7];
    const float* dw1 = (const float*)d_in[8];
    const float* db1 = (const float*)d_in[9];
    const float* dw2 = (const float*)d_in[10];
    const float* db2 = (const float*)d_in[11];
    const float* dw3 = (const float*)d_in[12];
    const float* db3 = (const float*)d_in[13];
    float* out = (float*)d_out;

    const int smem_enc2 = (18432 + 64) * 8;   // 147968 B
    const int smem_dec1 = (6144 + 64) * 8;    // 49664 B
    const int smem_dec2 = (12288 + 32) * 8;   // 98560 B
    cudaFuncSetAttribute(k_enc2, cudaFuncAttributeMaxDynamicSharedMemorySize, smem_enc2);
    cudaFuncSetAttribute(k_dec1, cudaFuncAttributeMaxDynamicSharedMemorySize, smem_dec1);
    cudaFuncSetAttribute(k_dec2, cudaFuncAttributeMaxDynamicSharedMemorySize, smem_dec2);

    k_enc1    <<<4096, 256>>>(x, ew1, eb1);
    k_enc2    <<<1024, 256, smem_enc2>>>(ew2, eb2);
    k_enc3_vq <<<1024, 256>>>(ew3, eb3, cb);
    k_dec1    <<<2048, 256, smem_dec1>>>(dw1, db1);
    k_dec2    <<<4096, 256, smem_dec2>>>(dw2, db2);
    k_dec3_mse<<<2048, 256>>>(dw3, db3, x);
    k_final   <<<1, 256>>>(out);
}

// round 8
// speedup vs baseline: 1.6483x; 1.6483x over previous
#include <cuda_runtime.h>

typedef unsigned long long ull;

// ---------------- scratch (device globals; no allocation allowed) ----------------
static __device__ __align__(16) float g_a1[64*32*128*128];          // enc1 out
static __device__ __align__(16) float g_a2[64*64*64*64];            // enc2 out
static __device__ __align__(16) float g_q [64*16*64*64];            // quantized (decoder input)
static __device__ __align__(16) float g_d1[64*64*128*128];          // dec1 out
static __device__ __align__(16) float g_d2[64*32*256*256];          // dec2 out
static __device__ float g_pvq [1024];                               // per-block VQ sq-sum
static __device__ float g_pmse[2048];                               // per-block recon sq-sum

// ---------------- f32x2 helpers ----------------
__device__ __forceinline__ ull pk2(float lo, float hi) {
    ull r;
    asm("mov.b64 %0, {%1, %2};" : "=l"(r)
        : "r"(__float_as_uint(lo)), "r"(__float_as_uint(hi)));
    return r;
}
__device__ __forceinline__ float2 upk2(ull p) {
    unsigned int a, b;
    asm("mov.b64 {%0, %1}, %2;" : "=r"(a), "=r"(b) : "l"(p));
    return make_float2(__uint_as_float(a), __uint_as_float(b));
}
__device__ __forceinline__ ull ffma2(ull a, ull b, ull c) {
    ull d;
    asm("fma.rn.f32x2 %0, %1, %2, %3;" : "=l"(d) : "l"(a), "l"(b), "l"(c));
    return d;
}

// ---------------- reduction helper ----------------
__device__ __forceinline__ float block_sum(float v, float* sred) {
    int lane = threadIdx.x & 31, w = threadIdx.x >> 5;
    #pragma unroll
    for (int o = 16; o > 0; o >>= 1) v += __shfl_down_sync(0xffffffffu, v, o);
    if (lane == 0) sred[w] = v;
    __syncthreads();
    if (w == 0) {
        v = (lane < (int)(blockDim.x >> 5)) ? sred[lane] : 0.f;
        #pragma unroll
        for (int o = 16; o > 0; o >>= 1) v += __shfl_down_sync(0xffffffffu, v, o);
    }
    return v;  // valid in thread 0
}

#define FMA4(ACC, J, V, W4)                         \
    do {                                            \
        ACC[4*(J)+0] = fmaf(V, (W4).x, ACC[4*(J)+0]); \
        ACC[4*(J)+1] = fmaf(V, (W4).y, ACC[4*(J)+1]); \
        ACC[4*(J)+2] = fmaf(V, (W4).z, ACC[4*(J)+2]); \
        ACC[4*(J)+3] = fmaf(V, (W4).w, ACC[4*(J)+3]); \
    } while (0)

// transposed-conv tap: pair weights layout wq.x=(w1,w2) wq.y=(0,w0)
template <int C>
__device__ __forceinline__ void ctap(float4 f, float v4, const ull* wp, ull* acc) {
    ull d0 = pk2(f.x, f.x), d1 = pk2(f.y, f.y), d2 = pk2(f.z, f.z), d3 = pk2(f.w, f.w);
    ull o0 = pk2(f.x, f.y), o1 = pk2(f.y, f.z), o2 = pk2(f.z, f.w), o3 = pk2(f.w, v4);
    #pragma unroll
    for (int oc = 0; oc < C; oc++) {
        ulonglong2 wq = *(const ulonglong2*)(wp + oc * 2);
        acc[oc*4+0] = ffma2(d0, wq.x, ffma2(o0, wq.y, acc[oc*4+0]));
        acc[oc*4+1] = ffma2(d1, wq.x, ffma2(o1, wq.y, acc[oc*4+1]));
        acc[oc*4+2] = ffma2(d2, wq.x, ffma2(o2, wq.y, acc[oc*4+2]));
        acc[oc*4+3] = ffma2(d3, wq.x, ffma2(o3, wq.y, acc[oc*4+3]));
    }
}

// scalar-weight tap for enc2: weights are plain floats, dup'd at use
template <int C>
__device__ __forceinline__ void stap(ull P0, ull P1, ull P2, ull P3,
                                     const float* wp, ull* acc) {
    #pragma unroll
    for (int oc = 0; oc < C; oc += 4) {
        float4 wf = *(const float4*)(wp + oc);
        ull w;
        w = pk2(wf.x, wf.x);
        acc[(oc+0)*4+0] = ffma2(P0, w, acc[(oc+0)*4+0]);
        acc[(oc+0)*4+1] = ffma2(P1, w, acc[(oc+0)*4+1]);
        acc[(oc+0)*4+2] = ffma2(P2, w, acc[(oc+0)*4+2]);
        acc[(oc+0)*4+3] = ffma2(P3, w, acc[(oc+0)*4+3]);
        w = pk2(wf.y, wf.y);
        acc[(oc+1)*4+0] = ffma2(P0, w, acc[(oc+1)*4+0]);
        acc[(oc+1)*4+1] = ffma2(P1, w, acc[(oc+1)*4+1]);
        acc[(oc+1)*4+2] = ffma2(P2, w, acc[(oc+1)*4+2]);
        acc[(oc+1)*4+3] = ffma2(P3, w, acc[(oc+1)*4+3]);
        w = pk2(wf.z, wf.z);
        acc[(oc+2)*4+0] = ffma2(P0, w, acc[(oc+2)*4+0]);
        acc[(oc+2)*4+1] = ffma2(P1, w, acc[(oc+2)*4+1]);
        acc[(oc+2)*4+2] = ffma2(P2, w, acc[(oc+2)*4+2]);
        acc[(oc+2)*4+3] = ffma2(P3, w, acc[(oc+2)*4+3]);
        w = pk2(wf.w, wf.w);
        acc[(oc+3)*4+0] = ffma2(P0, w, acc[(oc+3)*4+0]);
        acc[(oc+3)*4+1] = ffma2(P1, w, acc[(oc+3)*4+1]);
        acc[(oc+3)*4+2] = ffma2(P2, w, acc[(oc+3)*4+2]);
        acc[(oc+3)*4+3] = ffma2(P3, w, acc[(oc+3)*4+3]);
    }
}

// ---------------- enc1: conv 3->32, k3 s2 p1, ReLU ----------------
__global__ void __launch_bounds__(256) k_enc1(const float* __restrict__ x,
                                              const float* __restrict__ w,
                                              const float* __restrict__ bias) {
    __shared__ __align__(16) float s_w[27 * 32];
    __shared__ float s_b[32];
    for (int i = threadIdx.x; i < 27 * 32; i += 256) {
        int oc = i & 31, t = i >> 5;
        s_w[i] = w[oc * 27 + t];
    }
    if (threadIdx.x < 32) s_b[threadIdx.x] = bias[threadIdx.x];
    __syncthreads();

    int tid = blockIdx.x * 256 + threadIdx.x;
    int ow = tid & 127, oh = (tid >> 7) & 127, b = tid >> 14;

    float acc[32];
    #pragma unroll
    for (int oc = 0; oc < 32; oc++) acc[oc] = s_b[oc];

    #pragma unroll
    for (int ic = 0; ic < 3; ic++) {
        const float* xp = x + (size_t)(b * 3 + ic) * 65536;
        #pragma unroll
        for (int kh = 0; kh < 3; kh++) {
            int ih = oh * 2 + kh - 1;
            if ((unsigned)ih >= 256u) continue;
            #pragma unroll
            for (int kw = 0; kw < 3; kw++) {
                int iw = ow * 2 + kw - 1;
                if ((unsigned)iw >= 256u) continue;
                float v = xp[ih * 256 + iw];
                const float4* wp = (const float4*)&s_w[(ic * 9 + kh * 3 + kw) * 32];
                #pragma unroll
                for (int j = 0; j < 8; j++) { float4 w4 = wp[j]; FMA4(acc, j, v, w4); }
            }
        }
    }
    float* op = g_a1 + (size_t)b * 32 * 16384 + oh * 128 + ow;
    #pragma unroll
    for (int oc = 0; oc < 32; oc++) op[oc * 16384] = fmaxf(acc[oc], 0.f);
}

// ---------------- enc2: conv 32->64, k3 s2 p1, ReLU (P=8, C=8, plain-float weights) --
// block: chunk(8) x ocg(8) x row(4) = 256. grid: 64b * 16 rowgroups = 1024.
// smem 73.7KB -> 2 CTAs/SM.
__global__ void __launch_bounds__(256, 2) k_enc2(const float* __restrict__ w,
                                                 const float* __restrict__ bias) {
    extern __shared__ __align__(16) float smf[];
    float* s_w = smf;                       // 18432 floats [kh][ic][kw][oc]
    ull* s_bd = (ull*)(smf + 18432);        // 64 pairs
    for (int i = threadIdx.x; i < 18432; i += 256) {
        int oc = i & 63; int t = i >> 6; int kw = t % 3; t /= 3; int ic = t & 31; int kh = t >> 5;
        s_w[i] = w[((oc * 32 + ic) * 3 + kh) * 3 + kw];
    }
    if (threadIdx.x < 64) { float bv = bias[threadIdx.x]; s_bd[threadIdx.x] = pk2(bv, bv); }
    __syncthreads();

    int tx = threadIdx.x;
    int chunk = tx & 7, ocg = (tx >> 3) & 7, r = tx >> 6;
    int b = blockIdx.x >> 4, rg = blockIdx.x & 15;
    int oh = rg * 4 + r;
    int ocb = ocg * 8;
    int ow0 = chunk * 8;

    ull acc[32];
    #pragma unroll
    for (int oc = 0; oc < 8; oc++) {
        ull bp = s_bd[ocb + oc];
        acc[oc*4+0] = bp; acc[oc*4+1] = bp; acc[oc*4+2] = bp; acc[oc*4+3] = bp;
    }

    #pragma unroll 1
    for (int ic = 0; ic < 32; ic++) {
        const float* plane = g_a1 + (size_t)(b * 32 + ic) * 16384;
        #pragma unroll
        for (int kh = 0; kh < 3; kh++) {
            int ih = 2 * oh + kh - 1;
            if ((unsigned)ih >= 128u) continue;
            const float* row = plane + ih * 128 + chunk * 16;
            float vm1 = (chunk == 0) ? 0.f : row[-1];
            float4 g0 = *(const float4*)row;
            float4 g1 = *(const float4*)(row + 4);
            float4 g2 = *(const float4*)(row + 8);
            float4 g3 = *(const float4*)(row + 12);
            const float* wp = s_w + ((kh * 32 + ic) * 3) * 64 + ocb;
            // kw=0: (v[4j-1], v[4j+1])
            stap<8>(pk2(vm1,  g0.y), pk2(g0.w, g1.y), pk2(g1.w, g2.y), pk2(g2.w, g3.y), wp, acc);
            // kw=1: (v[4j],   v[4j+2])
            stap<8>(pk2(g0.x, g0.z), pk2(g1.x, g1.z), pk2(g2.x, g2.z), pk2(g3.x, g3.z), wp + 64, acc);
            // kw=2: (v[4j+1], v[4j+3])
            stap<8>(pk2(g0.y, g0.w), pk2(g1.y, g1.w), pk2(g2.y, g2.w), pk2(g3.y, g3.w), wp + 128, acc);
        }
    }

    float* op = g_a2 + ((size_t)(b * 64 + ocb) * 64 + oh) * 64 + ow0;
    #pragma unroll
    for (int oc = 0; oc < 8; oc++) {
        float2 p0 = upk2(acc[oc*4+0]), p1 = upk2(acc[oc*4+1]);
        float2 p2 = upk2(acc[oc*4+2]), p3 = upk2(acc[oc*4+3]);
        float4 lo = make_float4(fmaxf(p0.x,0.f), fmaxf(p0.y,0.f), fmaxf(p1.x,0.f), fmaxf(p1.y,0.f));
        float4 hi = make_float4(fmaxf(p2.x,0.f), fmaxf(p2.y,0.f), fmaxf(p3.x,0.f), fmaxf(p3.y,0.f));
        *(float4*)(op + (size_t)oc * 4096) = lo;
        *(float4*)(op + (size_t)oc * 4096 + 4) = hi;
    }
}

// ---------------- enc3 (1x1, 64->16) + VQ + q-loss (unchanged) ----------------
__global__ void __launch_bounds__(256) k_enc3_vq(const float* __restrict__ w3,
                                                 const float* __restrict__ b3,
                                                 const float* __restrict__ cb) {
    __shared__ __align__(16) float s_w[64 * 16];
    __shared__ float s_b[16];
    __shared__ __align__(16) float s_cb[512 * 16];
    __shared__ float s_cn[512];
    __shared__ float sred[32];

    for (int i = threadIdx.x; i < 1024; i += 256) {
        int d = i & 15, ic = i >> 4;
        s_w[i] = w3[d * 64 + ic];
    }
    if (threadIdx.x < 16) s_b[threadIdx.x] = b3[threadIdx.x];
    for (int i = threadIdx.x; i < 8192; i += 256) s_cb[i] = cb[i];
    __syncthreads();
    for (int j = threadIdx.x; j < 512; j += 256) {
        float s = 0.f;
        #pragma unroll
        for (int d = 0; d < 16; d++) { float c = s_cb[j * 16 + d]; s = fmaf(c, c, s); }
        s_cn[j] = s;
    }
    __syncthreads();

    int tid = blockIdx.x * 256 + threadIdx.x;
    int p = tid & 4095, b = tid >> 12;

    float z[16];
    #pragma unroll
    for (int d = 0; d < 16; d++) z[d] = s_b[d];
    const float* ap = g_a2 + (size_t)b * 64 * 4096 + p;
    #pragma unroll 8
    for (int ic = 0; ic < 64; ic++) {
        float v = ap[ic * 4096];
        const float4* wp = (const float4*)&s_w[ic * 16];
        #pragma unroll
        for (int j = 0; j < 4; j++) { float4 w4 = wp[j]; FMA4(z, j, v, w4); }
    }

    int best = 0; float bd = 3.4e38f;
    for (int j = 0; j < 512; j++) {
        const float4* cp = (const float4*)&s_cb[j * 16];
        float dot = 0.f;
        #pragma unroll
        for (int q4 = 0; q4 < 4; q4++) {
            float4 c4 = cp[q4];
            dot = fmaf(z[4*q4+0], c4.x, dot);
            dot = fmaf(z[4*q4+1], c4.y, dot);
            dot = fmaf(z[4*q4+2], c4.z, dot);
            dot = fmaf(z[4*q4+3], c4.w, dot);
        }
        float dist = s_cn[j] - 2.f * dot;
        if (dist < bd) { bd = dist; best = j; }
    }

    float sq = 0.f;
    float* qp = g_q + (size_t)b * 16 * 4096 + p;
    #pragma unroll
    for (int d = 0; d < 16; d++) {
        float qv = s_cb[best * 16 + d];
        float df = qv - z[d];
        sq = fmaf(df, df, sq);
        qp[d * 4096] = qv;
    }
    float bs = block_sum(sq, sred);
    if (threadIdx.x == 0) g_pvq[blockIdx.x] = bs;
}

// ---------------- dec1: convT 16->64 k3 s2 p1 op1, ReLU (C=8, 2 CTAs/SM) ------------
// block: chunk(16) x ocg(8) x r(2) = 256. grid: 64b * 2ph * 32rg = 4096.
__global__ void __launch_bounds__(256, 2) k_dec1(const float* __restrict__ w,
                                                 const float* __restrict__ bias) {
    extern __shared__ __align__(16) ull smu[];
    ull* s_w = smu;               // 6144: [kh][ic][oc] -> {(w1,w2),(0,w0)}
    ull* s_bd = smu + 6144;       // 64
    for (int i = threadIdx.x; i < 6144; i += 256) {
        int h = i & 1; int t = i >> 1; int oc = t & 63; int t2 = t >> 6; int ic = t2 & 15; int kh = t2 >> 4;
        const float* wb = w + ((ic * 64 + oc) * 3 + kh) * 3;   // dec_w1 [16][64][3][3]
        s_w[i] = h ? pk2(0.f, wb[0]) : pk2(wb[1], wb[2]);
    }
    if (threadIdx.x < 64) { float bv = bias[threadIdx.x]; s_bd[threadIdx.x] = pk2(bv, bv); }
    __syncthreads();

    int tx = threadIdx.x;
    int chunk = tx & 15, ocg = (tx >> 4) & 7, r = tx >> 7;
    int bi = blockIdx.x;
    int b = bi >> 6; int rem = bi & 63; int ph = rem >> 5; int rg = rem & 31;
    int R = rg * 2 + r;
    int oh = 2 * R + ph;
    int ocb = ocg * 8;
    int ow0 = chunk * 8;

    int nt, khs[2], ihs[2];
    if (ph == 0) { khs[0] = 1; ihs[0] = R; nt = 1; }
    else { khs[0] = 2; ihs[0] = R; nt = 1; if (R + 1 < 64) { khs[1] = 0; ihs[1] = R + 1; nt = 2; } }

    ull acc[32];
    #pragma unroll
    for (int oc = 0; oc < 8; oc++) {
        ull bp = s_bd[ocb + oc];
        acc[oc*4+0] = bp; acc[oc*4+1] = bp; acc[oc*4+2] = bp; acc[oc*4+3] = bp;
    }

    #pragma unroll 1
    for (int ic = 0; ic < 16; ic++) {
        const float* plane = g_q + (size_t)(b * 16 + ic) * 4096;
        for (int a = 0; a < nt; a++) {
            const float* row = plane + ihs[a] * 64 + chunk * 4;
            float4 f = *(const float4*)row;
            float v4 = (chunk < 15) ? row[4] : 0.f;
            ctap<8>(f, v4, s_w + ((khs[a] * 16 + ic) * 64 + ocb) * 2, acc);
        }
    }

    float* op = g_d1 + ((size_t)(b * 64 + ocb) * 128 + oh) * 128 + ow0;
    #pragma unroll
    for (int oc = 0; oc < 8; oc++) {
        float2 p0 = upk2(acc[oc*4+0]), p1 = upk2(acc[oc*4+1]);
        float2 p2 = upk2(acc[oc*4+2]), p3 = upk2(acc[oc*4+3]);
        float4 lo = make_float4(fmaxf(p0.x,0.f), fmaxf(p0.y,0.f), fmaxf(p1.x,0.f), fmaxf(p1.y,0.f));
        float4 hi = make_float4(fmaxf(p2.x,0.f), fmaxf(p2.y,0.f), fmaxf(p3.x,0.f), fmaxf(p3.y,0.f));
        *(float4*)(op + (size_t)oc * 16384) = lo;
        *(float4*)(op + (size_t)oc * 16384 + 4) = hi;
    }
}

// ---------------- dec2: convT 64->32 k3 s2 p1 op1, ReLU (C=8, 2 CTAs/SM) ------------
// block: chunk(32) x ocg(4) x r(2) = 256. grid: 64b * 2ph * 64rg = 8192.
__global__ void __launch_bounds__(256, 2) k_dec2(const float* __restrict__ w,
                                                 const float* __restrict__ bias) {
    extern __shared__ __align__(16) ull smu[];
    ull* s_w = smu;                // 12288: [kh][ic][oc] pairs
    ull* s_bd = smu + 12288;       // 32
    for (int i = threadIdx.x; i < 12288; i += 256) {
        int h = i & 1; int t = i >> 1; int oc = t & 31; int t2 = t >> 5; int ic = t2 & 63; int kh = t2 >> 6;
        const float* wb = w + ((ic * 32 + oc) * 3 + kh) * 3;   // dec_w2 [64][32][3][3]
        s_w[i] = h ? pk2(0.f, wb[0]) : pk2(wb[1], wb[2]);
    }
    if (threadIdx.x < 32) { float bv = bias[threadIdx.x]; s_bd[threadIdx.x] = pk2(bv, bv); }
    __syncthreads();

    int tx = threadIdx.x;
    int chunk = tx & 31, ocg = (tx >> 5) & 3, r = tx >> 7;
    int bi = blockIdx.x;
    int b = bi >> 7; int rem = bi & 127; int ph = rem >> 6; int rg = rem & 63;
    int R = rg * 2 + r;
    int oh = 2 * R + ph;
    int ocb = ocg * 8;
    int ow0 = chunk * 8;

    int nt, khs[2], ihs[2];
    if (ph == 0) { khs[0] = 1; ihs[0] = R; nt = 1; }
    else { khs[0] = 2; ihs[0] = R; nt = 1; if (R + 1 < 128) { khs[1] = 0; ihs[1] = R + 1; nt = 2; } }

    ull acc[32];
    #pragma unroll
    for (int oc = 0; oc < 8; oc++) {
        ull bp = s_bd[ocb + oc];
        acc[oc*4+0] = bp; acc[oc*4+1] = bp; acc[oc*4+2] = bp; acc[oc*4+3] = bp;
    }

    #pragma unroll 1
    for (int ic = 0; ic < 64; ic++) {
        const float* plane = g_d1 + (size_t)(b * 64 + ic) * 16384;
        for (int a = 0; a < nt; a++) {
            const float* row = plane + ihs[a] * 128 + chunk * 4;
            float4 f = *(const float4*)row;
            float v4 = (chunk < 31) ? row[4] : 0.f;
            ctap<8>(f, v4, s_w + ((khs[a] * 64 + ic) * 32 + ocb) * 2, acc);
        }
    }

    float* op = g_d2 + ((size_t)(b * 32 + ocb) * 256 + oh) * 256 + ow0;
    #pragma unroll
    for (int oc = 0; oc < 8; oc++) {
        float2 p0 = upk2(acc[oc*4+0]), p1 = upk2(acc[oc*4+1]);
        float2 p2 = upk2(acc[oc*4+2]), p3 = upk2(acc[oc*4+3]);
        float4 lo = make_float4(fmaxf(p0.x,0.f), fmaxf(p0.y,0.f), fmaxf(p1.x,0.f), fmaxf(p1.y,0.f));
        float4 hi = make_float4(fmaxf(p2.x,0.f), fmaxf(p2.y,0.f), fmaxf(p3.x,0.f), fmaxf(p3.y,0.f));
        *(float4*)(op + (size_t)oc * 65536) = lo;
        *(float4*)(op + (size_t)oc * 65536 + 4) = hi;
    }
}

// ---------------- dec3: convT 32->3 s1 p1 (== conv w/ flipped kernel) + fused MSE ----
__global__ void __launch_bounds__(256) k_dec3_mse(const float* __restrict__ w,
                                                  const float* __restrict__ bias,
                                                  const float* __restrict__ x) {
    __shared__ __align__(16) ull s_wd[864];   // [ic][kh][kw][oc] dup pairs
    __shared__ ull s_bd[3];
    __shared__ float sred[32];
    for (int i = threadIdx.x; i < 864; i += 256) {
        int oc = i % 3; int t = i / 3; int kw = t % 3; t /= 3; int kh = t % 3; int ic = t / 3;
        float wv = w[ic * 27 + oc * 9 + (2 - kh) * 3 + (2 - kw)];   // dec_w3 flipped
        s_wd[i] = pk2(wv, wv);
    }
    if (threadIdx.x < 3) { float bv = bias[threadIdx.x]; s_bd[threadIdx.x] = pk2(bv, bv); }
    __syncthreads();

    int tx = threadIdx.x;
    int chunk = tx & 31, r = tx >> 5;
    int b = blockIdx.x >> 5, rg = blockIdx.x & 31;
    int oh = rg * 8 + r;
    int ow0 = chunk * 8;

    ull acc[12];
    #pragma unroll
    for (int oc = 0; oc < 3; oc++) {
        ull bp = s_bd[oc];
        acc[oc*4+0] = bp; acc[oc*4+1] = bp; acc[oc*4+2] = bp; acc[oc*4+3] = bp;
    }

    #pragma unroll 1
    for (int ic = 0; ic < 32; ic++) {
        const float* plane = g_d2 + (size_t)(b * 32 + ic) * 65536;
        #pragma unroll
        for (int kh = 0; kh < 3; kh++) {
            int ih = oh + kh - 1;
            if ((unsigned)ih >= 256u) continue;
            const float* row = plane + ih * 256 + ow0;
            float4 f0 = *(const float4*)row;
            float4 f1 = *(const float4*)(row + 4);
            float vm1 = (chunk == 0) ? 0.f : row[-1];
            float v8  = (chunk == 31) ? 0.f : row[8];
            ull A0 = pk2(f0.x, f0.y), A1 = pk2(f0.z, f0.w), A2 = pk2(f1.x, f1.y), A3 = pk2(f1.z, f1.w);
            ull O0 = pk2(vm1, f0.x), O1 = pk2(f0.y, f0.z), O2 = pk2(f0.w, f1.x),
                O3 = pk2(f1.y, f1.z), O4 = pk2(f1.w, v8);
            const ull* wp = s_wd + (ic * 3 + kh) * 9;   // [kw][oc]
            #pragma unroll
            for (int oc = 0; oc < 3; oc++) {
                ull w0 = wp[oc], w1 = wp[3 + oc], w2 = wp[6 + oc];
                acc[oc*4+0] = ffma2(O0, w0, ffma2(A0, w1, ffma2(O1, w2, acc[oc*4+0])));
                acc[oc*4+1] = ffma2(O1, w0, ffma2(A1, w1, ffma2(O2, w2, acc[oc*4+1])));
                acc[oc*4+2] = ffma2(O2, w0, ffma2(A2, w1, ffma2(O3, w2, acc[oc*4+2])));
                acc[oc*4+3] = ffma2(O3, w0, ffma2(A3, w1, ffma2(O4, w2, acc[oc*4+3])));
            }
        }
    }

    const float* xp = x + (size_t)b * 3 * 65536 + oh * 256 + ow0;
    float sq = 0.f;
    #pragma unroll
    for (int oc = 0; oc < 3; oc++) {
        float4 x0 = *(const float4*)(xp + (size_t)oc * 65536);
        float4 x1 = *(const float4*)(xp + (size_t)oc * 65536 + 4);
        float2 p0 = upk2(acc[oc*4+0]), p1 = upk2(acc[oc*4+1]);
        float2 p2 = upk2(acc[oc*4+2]), p3 = upk2(acc[oc*4+3]);
        float e;
        e = p0.x - x0.x; sq = fmaf(e, e, sq);
        e = p0.y - x0.y; sq = fmaf(e, e, sq);
        e = p1.x - x0.z; sq = fmaf(e, e, sq);
        e = p1.y - x0.w; sq = fmaf(e, e, sq);
        e = p2.x - x1.x; sq = fmaf(e, e, sq);
        e = p2.y - x1.y; sq = fmaf(e, e, sq);
        e = p3.x - x1.z; sq = fmaf(e, e, sq);
        e = p3.y - x1.w; sq = fmaf(e, e, sq);
    }
    float bs = block_sum(sq, sred);
    if (threadIdx.x == 0) g_pmse[blockIdx.x] = bs;
}

// ---------------- deterministic final reduction ----------------
__global__ void k_final(float* __restrict__ out) {
    __shared__ double sd[256];
    double s1 = 0.0, s2 = 0.0;
    for (int i = threadIdx.x; i < 1024; i += 256) s1 += (double)g_pvq[i];
    for (int i = threadIdx.x; i < 2048; i += 256) s2 += (double)g_pmse[i];
    sd[threadIdx.x] = s1; __syncthreads();
    for (int o = 128; o > 0; o >>= 1) {
        if ((int)threadIdx.x < o) sd[threadIdx.x] += sd[threadIdx.x + o];
        __syncthreads();
    }
    double vq = sd[0]; __syncthreads();
    sd[threadIdx.x] = s2; __syncthreads();
    for (int o = 128; o > 0; o >>= 1) {
        if ((int)threadIdx.x < o) sd[threadIdx.x] += sd[threadIdx.x + o];
        __syncthreads();
    }
    if (threadIdx.x == 0) {
        double mq = vq / 4194304.0;                 // 64*64*64*16
        double mr = sd[0] / 12582912.0;             // 64*3*256*256
        out[0] = (float)(1.25 * mq);
        out[1] = (float)mr;
        out[2] = (float)mr;
    }
}

// ---------------- launch ----------------
extern "C" void kernel_launch(void* const* d_in, const int* in_sizes, int n_in,
                              void* d_out, int out_size) {
    const float* x   = (const float*)d_in[0];
    const float* ew1 = (const float*)d_in[1];
    const float* eb1 = (const float*)d_in[2];
    const float* ew2 = (const float*)d_in[3];
    const float* eb2 = (const float*)d_in[4];
    const float* ew3 = (const float*)d_in[5];
    const float* eb3 = (const float*)d_in[6];
    const float* cb  = (const float*)d_in[7];
    const float* dw1 = (const float*)d_in[8];
    const float* db1 = (const float*)d_in[9];
    const float* dw2 = (const float*)d_in[10];
    const float* db2 = (const float*)d_in[11];
    const float* dw3 = (const float*)d_in[12];
    const float* db3 = (const float*)d_in[13];
    float* out = (float*)d_out;

    const int smem_enc2 = 18432 * 4 + 64 * 8;  // 74240 B
    const int smem_dec1 = (6144 + 64) * 8;     // 49664 B
    const int smem_dec2 = (12288 + 32) * 8;    // 98560 B
    cudaFuncSetAttribute(k_enc2, cudaFuncAttributeMaxDynamicSharedMemorySize, smem_enc2);
    cudaFuncSetAttribute(k_dec1, cudaFuncAttributeMaxDynamicSharedMemorySize, smem_dec1);
    cudaFuncSetAttribute(k_dec2, cudaFuncAttributeMaxDynamicSharedMemorySize, smem_dec2);

    k_enc1    <<<4096, 256>>>(x, ew1, eb1);
    k_enc2    <<<1024, 256, smem_enc2>>>(ew2, eb2);
    k_enc3_vq <<<1024, 256>>>(ew3, eb3, cb);
    k_dec1    <<<4096, 256, smem_dec1>>>(dw1, db1);
    k_dec2    <<<8192, 256, smem_dec2>>>(dw2, db2);
    k_dec3_mse<<<2048, 256>>>(dw3, db3, x);
    k_final   <<<1, 256>>>(out);
}

// round 9
// speedup vs baseline: 1.8296x; 1.1100x over previous
#include <cuda_runtime.h>

typedef unsigned long long ull;

// ---------------- scratch (device globals; no allocation allowed) ----------------
static __device__ __align__(16) float g_a1[64*32*128*128];          // enc1 out
static __device__ __align__(16) float g_a2[64*64*64*64];            // enc2 out
static __device__ __align__(16) float g_q [64*16*64*64];            // quantized (decoder input)
static __device__ __align__(16) float g_d1[64*64*128*128];          // dec1 out
static __device__ __align__(16) float g_d2[64*32*256*256];          // dec2 out
static __device__ float g_pvq [1024];                               // per-block VQ sq-sum
static __device__ float g_pmse[2048];                               // per-block recon sq-sum

// ---------------- f32x2 helpers ----------------
__device__ __forceinline__ ull pk2(float lo, float hi) {
    ull r;
    asm("mov.b64 %0, {%1, %2};" : "=l"(r)
        : "r"(__float_as_uint(lo)), "r"(__float_as_uint(hi)));
    return r;
}
__device__ __forceinline__ float2 upk2(ull p) {
    unsigned int a, b;
    asm("mov.b64 {%0, %1}, %2;" : "=r"(a), "=r"(b) : "l"(p));
    return make_float2(__uint_as_float(a), __uint_as_float(b));
}
__device__ __forceinline__ ull ffma2(ull a, ull b, ull c) {
    ull d;
    asm("fma.rn.f32x2 %0, %1, %2, %3;" : "=l"(d) : "l"(a), "l"(b), "l"(c));
    return d;
}
__device__ __forceinline__ float4 z4() { return make_float4(0.f, 0.f, 0.f, 0.f); }

// ---------------- reduction helper ----------------
__device__ __forceinline__ float block_sum(float v, float* sred) {
    int lane = threadIdx.x & 31, w = threadIdx.x >> 5;
    #pragma unroll
    for (int o = 16; o > 0; o >>= 1) v += __shfl_down_sync(0xffffffffu, v, o);
    if (lane == 0) sred[w] = v;
    __syncthreads();
    if (w == 0) {
        v = (lane < (int)(blockDim.x >> 5)) ? sred[lane] : 0.f;
        #pragma unroll
        for (int o = 16; o > 0; o >>= 1) v += __shfl_down_sync(0xffffffffu, v, o);
    }
    return v;  // valid in thread 0
}

#define FMA4(ACC, J, V, W4)                         \
    do {                                            \
        ACC[4*(J)+0] = fmaf(V, (W4).x, ACC[4*(J)+0]); \
        ACC[4*(J)+1] = fmaf(V, (W4).y, ACC[4*(J)+1]); \
        ACC[4*(J)+2] = fmaf(V, (W4).z, ACC[4*(J)+2]); \
        ACC[4*(J)+3] = fmaf(V, (W4).w, ACC[4*(J)+3]); \
    } while (0)

// transposed-conv tap: pair weights layout wq.x=(w1,w2) wq.y=(0,w0)
template <int C>
__device__ __forceinline__ void ctap(float4 f, float v4, const ull* wp, ull* acc) {
    ull d0 = pk2(f.x, f.x), d1 = pk2(f.y, f.y), d2 = pk2(f.z, f.z), d3 = pk2(f.w, f.w);
    ull o0 = pk2(f.x, f.y), o1 = pk2(f.y, f.z), o2 = pk2(f.z, f.w), o3 = pk2(f.w, v4);
    #pragma unroll
    for (int oc = 0; oc < C; oc++) {
        ulonglong2 wq = *(const ulonglong2*)(wp + oc * 2);
        acc[oc*4+0] = ffma2(d0, wq.x, ffma2(o0, wq.y, acc[oc*4+0]));
        acc[oc*4+1] = ffma2(d1, wq.x, ffma2(o1, wq.y, acc[oc*4+1]));
        acc[oc*4+2] = ffma2(d2, wq.x, ffma2(o2, wq.y, acc[oc*4+2]));
        acc[oc*4+3] = ffma2(d3, wq.x, ffma2(o3, wq.y, acc[oc*4+3]));
    }
}

// scalar-weight tap for enc2: weights are plain floats, dup'd at use
template <int C>
__device__ __forceinline__ void stap(ull P0, ull P1, ull P2, ull P3,
                                     const float* wp, ull* acc) {
    #pragma unroll
    for (int oc = 0; oc < C; oc += 4) {
        float4 wf = *(const float4*)(wp + oc);
        ull w;
        w = pk2(wf.x, wf.x);
        acc[(oc+0)*4+0] = ffma2(P0, w, acc[(oc+0)*4+0]);
        acc[(oc+0)*4+1] = ffma2(P1, w, acc[(oc+0)*4+1]);
        acc[(oc+0)*4+2] = ffma2(P2, w, acc[(oc+0)*4+2]);
        acc[(oc+0)*4+3] = ffma2(P3, w, acc[(oc+0)*4+3]);
        w = pk2(wf.y, wf.y);
        acc[(oc+1)*4+0] = ffma2(P0, w, acc[(oc+1)*4+0]);
        acc[(oc+1)*4+1] = ffma2(P1, w, acc[(oc+1)*4+1]);
        acc[(oc+1)*4+2] = ffma2(P2, w, acc[(oc+1)*4+2]);
        acc[(oc+1)*4+3] = ffma2(P3, w, acc[(oc+1)*4+3]);
        w = pk2(wf.z, wf.z);
        acc[(oc+2)*4+0] = ffma2(P0, w, acc[(oc+2)*4+0]);
        acc[(oc+2)*4+1] = ffma2(P1, w, acc[(oc+2)*4+1]);
        acc[(oc+2)*4+2] = ffma2(P2, w, acc[(oc+2)*4+2]);
        acc[(oc+2)*4+3] = ffma2(P3, w, acc[(oc+2)*4+3]);
        w = pk2(wf.w, wf.w);
        acc[(oc+3)*4+0] = ffma2(P0, w, acc[(oc+3)*4+0]);
        acc[(oc+3)*4+1] = ffma2(P1, w, acc[(oc+3)*4+1]);
        acc[(oc+3)*4+2] = ffma2(P2, w, acc[(oc+3)*4+2]);
        acc[(oc+3)*4+3] = ffma2(P3, w, acc[(oc+3)*4+3]);
    }
}

// ---------------- enc1: conv 3->32, k3 s2 p1, ReLU ----------------
__global__ void __launch_bounds__(256) k_enc1(const float* __restrict__ x,
                                              const float* __restrict__ w,
                                              const float* __restrict__ bias) {
    __shared__ __align__(16) float s_w[27 * 32];
    __shared__ float s_b[32];
    for (int i = threadIdx.x; i < 27 * 32; i += 256) {
        int oc = i & 31, t = i >> 5;
        s_w[i] = w[oc * 27 + t];
    }
    if (threadIdx.x < 32) s_b[threadIdx.x] = bias[threadIdx.x];
    __syncthreads();

    int tid = blockIdx.x * 256 + threadIdx.x;
    int ow = tid & 127, oh = (tid >> 7) & 127, b = tid >> 14;

    float acc[32];
    #pragma unroll
    for (int oc = 0; oc < 32; oc++) acc[oc] = s_b[oc];

    #pragma unroll
    for (int ic = 0; ic < 3; ic++) {
        const float* xp = x + (size_t)(b * 3 + ic) * 65536;
        #pragma unroll
        for (int kh = 0; kh < 3; kh++) {
            int ih = oh * 2 + kh - 1;
            if ((unsigned)ih >= 256u) continue;
            #pragma unroll
            for (int kw = 0; kw < 3; kw++) {
                int iw = ow * 2 + kw - 1;
                if ((unsigned)iw >= 256u) continue;
                float v = xp[ih * 256 + iw];
                const float4* wp = (const float4*)&s_w[(ic * 9 + kh * 3 + kw) * 32];
                #pragma unroll
                for (int j = 0; j < 8; j++) { float4 w4 = wp[j]; FMA4(acc, j, v, w4); }
            }
        }
    }
    float* op = g_a1 + (size_t)b * 32 * 16384 + oh * 128 + ow;
    #pragma unroll
    for (int oc = 0; oc < 32; oc++) op[oc * 16384] = fmaxf(acc[oc], 0.f);
}

// ---------------- enc2: conv 32->64, k3 s2 p1, ReLU (P=8, C=8, plain-float weights) --
__global__ void __launch_bounds__(256, 2) k_enc2(const float* __restrict__ w,
                                                 const float* __restrict__ bias) {
    extern __shared__ __align__(16) float smf[];
    float* s_w = smf;                       // 18432 floats [kh][ic][kw][oc]
    ull* s_bd = (ull*)(smf + 18432);        // 64 pairs
    for (int i = threadIdx.x; i < 18432; i += 256) {
        int oc = i & 63; int t = i >> 6; int kw = t % 3; t /= 3; int ic = t & 31; int kh = t >> 5;
        s_w[i] = w[((oc * 32 + ic) * 3 + kh) * 3 + kw];
    }
    if (threadIdx.x < 64) { float bv = bias[threadIdx.x]; s_bd[threadIdx.x] = pk2(bv, bv); }
    __syncthreads();

    int tx = threadIdx.x;
    int chunk = tx & 7, ocg = (tx >> 3) & 7, r = tx >> 6;
    int b = blockIdx.x >> 4, rg = blockIdx.x & 15;
    int oh = rg * 4 + r;
    int ocb = ocg * 8;
    int ow0 = chunk * 8;

    ull acc[32];
    #pragma unroll
    for (int oc = 0; oc < 8; oc++) {
        ull bp = s_bd[ocb + oc];
        acc[oc*4+0] = bp; acc[oc*4+1] = bp; acc[oc*4+2] = bp; acc[oc*4+3] = bp;
    }

    #pragma unroll 1
    for (int ic = 0; ic < 32; ic++) {
        const float* plane = g_a1 + (size_t)(b * 32 + ic) * 16384;
        #pragma unroll
        for (int kh = 0; kh < 3; kh++) {
            int ih = 2 * oh + kh - 1;
            if ((unsigned)ih >= 128u) continue;
            const float* row = plane + ih * 128 + chunk * 16;
            float vm1 = (chunk == 0) ? 0.f : row[-1];
            float4 g0 = *(const float4*)row;
            float4 g1 = *(const float4*)(row + 4);
            float4 g2 = *(const float4*)(row + 8);
            float4 g3 = *(const float4*)(row + 12);
            const float* wp = s_w + ((kh * 32 + ic) * 3) * 64 + ocb;
            stap<8>(pk2(vm1,  g0.y), pk2(g0.w, g1.y), pk2(g1.w, g2.y), pk2(g2.w, g3.y), wp, acc);
            stap<8>(pk2(g0.x, g0.z), pk2(g1.x, g1.z), pk2(g2.x, g2.z), pk2(g3.x, g3.z), wp + 64, acc);
            stap<8>(pk2(g0.y, g0.w), pk2(g1.y, g1.w), pk2(g2.y, g2.w), pk2(g3.y, g3.w), wp + 128, acc);
        }
    }

    float* op = g_a2 + ((size_t)(b * 64 + ocb) * 64 + oh) * 64 + ow0;
    #pragma unroll
    for (int oc = 0; oc < 8; oc++) {
        float2 p0 = upk2(acc[oc*4+0]), p1 = upk2(acc[oc*4+1]);
        float2 p2 = upk2(acc[oc*4+2]), p3 = upk2(acc[oc*4+3]);
        float4 lo = make_float4(fmaxf(p0.x,0.f), fmaxf(p0.y,0.f), fmaxf(p1.x,0.f), fmaxf(p1.y,0.f));
        float4 hi = make_float4(fmaxf(p2.x,0.f), fmaxf(p2.y,0.f), fmaxf(p3.x,0.f), fmaxf(p3.y,0.f));
        *(float4*)(op + (size_t)oc * 4096) = lo;
        *(float4*)(op + (size_t)oc * 4096 + 4) = hi;
    }
}

// ---------------- enc3 (1x1, 64->16) + VQ + q-loss (unchanged) ----------------
__global__ void __launch_bounds__(256) k_enc3_vq(const float* __restrict__ w3,
                                                 const float* __restrict__ b3,
                                                 const float* __restrict__ cb) {
    __shared__ __align__(16) float s_w[64 * 16];
    __shared__ float s_b[16];
    __shared__ __align__(16) float s_cb[512 * 16];
    __shared__ float s_cn[512];
    __shared__ float sred[32];

    for (int i = threadIdx.x; i < 1024; i += 256) {
        int d = i & 15, ic = i >> 4;
        s_w[i] = w3[d * 64 + ic];
    }
    if (threadIdx.x < 16) s_b[threadIdx.x] = b3[threadIdx.x];
    for (int i = threadIdx.x; i < 8192; i += 256) s_cb[i] = cb[i];
    __syncthreads();
    for (int j = threadIdx.x; j < 512; j += 256) {
        float s = 0.f;
        #pragma unroll
        for (int d = 0; d < 16; d++) { float c = s_cb[j * 16 + d]; s = fmaf(c, c, s); }
        s_cn[j] = s;
    }
    __syncthreads();

    int tid = blockIdx.x * 256 + threadIdx.x;
    int p = tid & 4095, b = tid >> 12;

    float z[16];
    #pragma unroll
    for (int d = 0; d < 16; d++) z[d] = s_b[d];
    const float* ap = g_a2 + (size_t)b * 64 * 4096 + p;
    #pragma unroll 8
    for (int ic = 0; ic < 64; ic++) {
        float v = ap[ic * 4096];
        const float4* wp = (const float4*)&s_w[ic * 16];
        #pragma unroll
        for (int j = 0; j < 4; j++) { float4 w4 = wp[j]; FMA4(z, j, v, w4); }
    }

    int best = 0; float bd = 3.4e38f;
    for (int j = 0; j < 512; j++) {
        const float4* cp = (const float4*)&s_cb[j * 16];
        float dot = 0.f;
        #pragma unroll
        for (int q4 = 0; q4 < 4; q4++) {
            float4 c4 = cp[q4];
            dot = fmaf(z[4*q4+0], c4.x, dot);
            dot = fmaf(z[4*q4+1], c4.y, dot);
            dot = fmaf(z[4*q4+2], c4.z, dot);
            dot = fmaf(z[4*q4+3], c4.w, dot);
        }
        float dist = s_cn[j] - 2.f * dot;
        if (dist < bd) { bd = dist; best = j; }
    }

    float sq = 0.f;
    float* qp = g_q + (size_t)b * 16 * 4096 + p;
    #pragma unroll
    for (int d = 0; d < 16; d++) {
        float qv = s_cb[best * 16 + d];
        float df = qv - z[d];
        sq = fmaf(df, df, sq);
        qp[d * 4096] = qv;
    }
    float bs = block_sum(sq, sred);
    if (threadIdx.x == 0) g_pvq[blockIdx.x] = bs;
}

// ---------------- dec1: convT 16->64 k3 s2 p1 op1, ReLU (C=8, 2CTA, ic-unroll2) ------
// block: chunk(16) x ocg(8) x r(2) = 256. grid: 64b * 2ph * 32rg = 4096.
__global__ void __launch_bounds__(256, 2) k_dec1(const float* __restrict__ w,
                                                 const float* __restrict__ bias) {
    extern __shared__ __align__(16) ull smu[];
    ull* s_w = smu;               // 6144: [kh][ic][oc] -> {(w1,w2),(0,w0)}
    ull* s_bd = smu + 6144;       // 64
    for (int i = threadIdx.x; i < 6144; i += 256) {
        int h = i & 1; int t = i >> 1; int oc = t & 63; int t2 = t >> 6; int ic = t2 & 15; int kh = t2 >> 4;
        const float* wb = w + ((ic * 64 + oc) * 3 + kh) * 3;   // dec_w1 [16][64][3][3]
        s_w[i] = h ? pk2(0.f, wb[0]) : pk2(wb[1], wb[2]);
    }
    if (threadIdx.x < 64) { float bv = bias[threadIdx.x]; s_bd[threadIdx.x] = pk2(bv, bv); }
    __syncthreads();

    int tx = threadIdx.x;
    int chunk = tx & 15, ocg = (tx >> 4) & 7, r = tx >> 7;
    int bi = blockIdx.x;
    int b = bi >> 6; int rem = bi & 63; int ph = rem >> 5; int rg = rem & 31;
    int R = rg * 2 + r;
    int oh = 2 * R + ph;
    int ocb = ocg * 8;
    int ow0 = chunk * 8;

    ull acc[32];
    #pragma unroll
    for (int oc = 0; oc < 8; oc++) {
        ull bp = s_bd[ocb + oc];
        acc[oc*4+0] = bp; acc[oc*4+1] = bp; acc[oc*4+2] = bp; acc[oc*4+3] = bp;
    }

    const float* base = g_q + (size_t)b * 16 * 4096 + chunk * 4;
    bool edge = (chunk < 15);

    if (ph == 0) {                 // single tap kh=1 @ row R; ic-unroll 2 (MLP=2)
        const float* p0 = base + R * 64;
        #pragma unroll 1
        for (int ic = 0; ic < 16; ic += 2) {
            const float* ra = p0 + ic * 4096;
            const float* rb = ra + 4096;
            float4 fa = *(const float4*)ra; float va = edge ? ra[4] : 0.f;
            float4 fb = *(const float4*)rb; float vb = edge ? rb[4] : 0.f;
            ctap<8>(fa, va, s_w + ((1 * 16 + ic)     * 64 + ocb) * 2, acc);
            ctap<8>(fb, vb, s_w + ((1 * 16 + ic + 1) * 64 + ocb) * 2, acc);
        }
    } else {                       // taps kh=2 @ R, kh=0 @ R+1; ic-unroll 2 (MLP=4)
        bool ok = (R + 1 < 64);
        const float* pa = base + R * 64;
        const float* pb = base + (R + 1) * 64;
        #pragma unroll 1
        for (int ic = 0; ic < 16; ic += 2) {
            const float* ra0 = pa + ic * 4096;
            const float* ra1 = ra0 + 4096;
            const float* rb0 = pb + ic * 4096;
            const float* rb1 = rb0 + 4096;
            float4 fa0 = *(const float4*)ra0; float va0 = edge ? ra0[4] : 0.f;
            float4 fa1 = *(const float4*)ra1; float va1 = edge ? ra1[4] : 0.f;
            float4 fb0 = ok ? *(const float4*)rb0 : z4(); float vb0 = (ok && edge) ? rb0[4] : 0.f;
            float4 fb1 = ok ? *(const float4*)rb1 : z4(); float vb1 = (ok && edge) ? rb1[4] : 0.f;
            ctap<8>(fa0, va0, s_w + ((2 * 16 + ic)     * 64 + ocb) * 2, acc);
            ctap<8>(fb0, vb0, s_w + ((0 * 16 + ic)     * 64 + ocb) * 2, acc);
            ctap<8>(fa1, va1, s_w + ((2 * 16 + ic + 1) * 64 + ocb) * 2, acc);
            ctap<8>(fb1, vb1, s_w + ((0 * 16 + ic + 1) * 64 + ocb) * 2, acc);
        }
    }

    float* op = g_d1 + ((size_t)(b * 64 + ocb) * 128 + oh) * 128 + ow0;
    #pragma unroll
    for (int oc = 0; oc < 8; oc++) {
        float2 p0 = upk2(acc[oc*4+0]), p1 = upk2(acc[oc*4+1]);
        float2 p2 = upk2(acc[oc*4+2]), p3 = upk2(acc[oc*4+3]);
        float4 lo = make_float4(fmaxf(p0.x,0.f), fmaxf(p0.y,0.f), fmaxf(p1.x,0.f), fmaxf(p1.y,0.f));
        float4 hi = make_float4(fmaxf(p2.x,0.f), fmaxf(p2.y,0.f), fmaxf(p3.x,0.f), fmaxf(p3.y,0.f));
        *(float4*)(op + (size_t)oc * 16384) = lo;
        *(float4*)(op + (size_t)oc * 16384 + 4) = hi;
    }
}

// ---------------- dec2: convT 64->32 k3 s2 p1 op1, ReLU (C=8, 2CTA, ic-unroll2) ------
// block: chunk(32) x ocg(4) x r(2) = 256. grid: 64b * 2ph * 64rg = 8192.
__global__ void __launch_bounds__(256, 2) k_dec2(const float* __restrict__ w,
                                                 const float* __restrict__ bias) {
    extern __shared__ __align__(16) ull smu[];
    ull* s_w = smu;                // 12288: [kh][ic][oc] pairs
    ull* s_bd = smu + 12288;       // 32
    for (int i = threadIdx.x; i < 12288; i += 256) {
        int h = i & 1; int t = i >> 1; int oc = t & 31; int t2 = t >> 5; int ic = t2 & 63; int kh = t2 >> 6;
        const float* wb = w + ((ic * 32 + oc) * 3 + kh) * 3;   // dec_w2 [64][32][3][3]
        s_w[i] = h ? pk2(0.f, wb[0]) : pk2(wb[1], wb[2]);
    }
    if (threadIdx.x < 32) { float bv = bias[threadIdx.x]; s_bd[threadIdx.x] = pk2(bv, bv); }
    __syncthreads();

    int tx = threadIdx.x;
    int chunk = tx & 31, ocg = (tx >> 5) & 3, r = tx >> 7;
    int bi = blockIdx.x;
    int b = bi >> 7; int rem = bi & 127; int ph = rem >> 6; int rg = rem & 63;
    int R = rg * 2 + r;
    int oh = 2 * R + ph;
    int ocb = ocg * 8;
    int ow0 = chunk * 8;

    ull acc[32];
    #pragma unroll
    for (int oc = 0; oc < 8; oc++) {
        ull bp = s_bd[ocb + oc];
        acc[oc*4+0] = bp; acc[oc*4+1] = bp; acc[oc*4+2] = bp; acc[oc*4+3] = bp;
    }

    const float* base = g_d1 + (size_t)b * 64 * 16384 + chunk * 4;
    bool edge = (chunk < 31);

    if (ph == 0) {                 // single tap kh=1 @ row R; ic-unroll 2 (MLP=2)
        const float* p0 = base + R * 128;
        #pragma unroll 1
        for (int ic = 0; ic < 64; ic += 2) {
            const float* ra = p0 + (size_t)ic * 16384;
            const float* rb = ra + 16384;
            float4 fa = *(const float4*)ra; float va = edge ? ra[4] : 0.f;
            float4 fb = *(const float4*)rb; float vb = edge ? rb[4] : 0.f;
            ctap<8>(fa, va, s_w + ((1 * 64 + ic)     * 32 + ocb) * 2, acc);
            ctap<8>(fb, vb, s_w + ((1 * 64 + ic + 1) * 32 + ocb) * 2, acc);
        }
    } else {                       // taps kh=2 @ R, kh=0 @ R+1; ic-unroll 2 (MLP=4)
        bool ok = (R + 1 < 128);
        const float* pa = base + R * 128;
        const float* pb = base + (R + 1) * 128;
        #pragma unroll 1
        for (int ic = 0; ic < 64; ic += 2) {
            const float* ra0 = pa + (size_t)ic * 16384;
            const float* ra1 = ra0 + 16384;
            const float* rb0 = pb + (size_t)ic * 16384;
            const float* rb1 = rb0 + 16384;
            float4 fa0 = *(const float4*)ra0; float va0 = edge ? ra0[4] : 0.f;
            float4 fa1 = *(const float4*)ra1; float va1 = edge ? ra1[4] : 0.f;
            float4 fb0 = ok ? *(const float4*)rb0 : z4(); float vb0 = (ok && edge) ? rb0[4] : 0.f;
            float4 fb1 = ok ? *(const float4*)rb1 : z4(); float vb1 = (ok && edge) ? rb1[4] : 0.f;
            ctap<8>(fa0, va0, s_w + ((2 * 64 + ic)     * 32 + ocb) * 2, acc);
            ctap<8>(fb0, vb0, s_w + ((0 * 64 + ic)     * 32 + ocb) * 2, acc);
            ctap<8>(fa1, va1, s_w + ((2 * 64 + ic + 1) * 32 + ocb) * 2, acc);
            ctap<8>(fb1, vb1, s_w + ((0 * 64 + ic + 1) * 32 + ocb) * 2, acc);
        }
    }

    float* op = g_d2 + ((size_t)(b * 32 + ocb) * 256 + oh) * 256 + ow0;
    #pragma unroll
    for (int oc = 0; oc < 8; oc++) {
        float2 p0 = upk2(acc[oc*4+0]), p1 = upk2(acc[oc*4+1]);
        float2 p2 = upk2(acc[oc*4+2]), p3 = upk2(acc[oc*4+3]);
        float4 lo = make_float4(fmaxf(p0.x,0.f), fmaxf(p0.y,0.f), fmaxf(p1.x,0.f), fmaxf(p1.y,0.f));
        float4 hi = make_float4(fmaxf(p2.x,0.f), fmaxf(p2.y,0.f), fmaxf(p3.x,0.f), fmaxf(p3.y,0.f));
        *(float4*)(op + (size_t)oc * 65536) = lo;
        *(float4*)(op + (size_t)oc * 65536 + 4) = hi;
    }
}

// ---------------- dec3: convT 32->3 s1 p1 + fused MSE (3-kh batched loads, MLP=6) ----
__global__ void __launch_bounds__(256) k_dec3_mse(const float* __restrict__ w,
                                                  const float* __restrict__ bias,
                                                  const float* __restrict__ x) {
    __shared__ __align__(16) ull s_wd[864];   // [ic][kh][kw][oc] dup pairs
    __shared__ ull s_bd[3];
    __shared__ float sred[32];
    for (int i = threadIdx.x; i < 864; i += 256) {
        int oc = i % 3; int t = i / 3; int kw = t % 3; t /= 3; int kh = t % 3; int ic = t / 3;
        float wv = w[ic * 27 + oc * 9 + (2 - kh) * 3 + (2 - kw)];   // dec_w3 flipped
        s_wd[i] = pk2(wv, wv);
    }
    if (threadIdx.x < 3) { float bv = bias[threadIdx.x]; s_bd[threadIdx.x] = pk2(bv, bv); }
    __syncthreads();

    int tx = threadIdx.x;
    int chunk = tx & 31, r = tx >> 5;
    int b = blockIdx.x >> 5, rg = blockIdx.x & 31;
    int oh = rg * 8 + r;
    int ow0 = chunk * 8;

    bool ok0 = (oh > 0), ok2 = (oh < 255);
    bool eL = (chunk != 0), eR = (chunk != 31);

    ull acc[12];
    #pragma unroll
    for (int oc = 0; oc < 3; oc++) {
        ull bp = s_bd[oc];
        acc[oc*4+0] = bp; acc[oc*4+1] = bp; acc[oc*4+2] = bp; acc[oc*4+3] = bp;
    }

    #pragma unroll 1
    for (int ic = 0; ic < 32; ic++) {
        const float* rowm = g_d2 + (size_t)(b * 32 + ic) * 65536 + (oh - 1) * 256 + ow0;
        // batch all 6 main loads (MLP=6); predicate-zero boundary rows
        float4 m0 = ok0 ? *(const float4*)rowm       : z4();
        float4 m1 = ok0 ? *(const float4*)(rowm + 4) : z4();
        float4 c0 = *(const float4*)(rowm + 256);
        float4 c1 = *(const float4*)(rowm + 260);
        float4 b0 = ok2 ? *(const float4*)(rowm + 512) : z4();
        float4 b1 = ok2 ? *(const float4*)(rowm + 516) : z4();
        float mm1 = (ok0 && eL) ? rowm[-1]  : 0.f;
        float m8  = (ok0 && eR) ? rowm[8]   : 0.f;
        float cm1 = eL          ? rowm[255] : 0.f;
        float c8  = eR          ? rowm[264] : 0.f;
        float bm1 = (ok2 && eL) ? rowm[511] : 0.f;
        float b8  = (ok2 && eR) ? rowm[520] : 0.f;

        const ull* wp = s_wd + ic * 27;   // [kh][kw][oc]
        #pragma unroll
        for (int kh = 0; kh < 3; kh++) {
            float4 f0 = (kh == 0) ? m0 : (kh == 1) ? c0 : b0;
            float4 f1 = (kh == 0) ? m1 : (kh == 1) ? c1 : b1;
            float vm1 = (kh == 0) ? mm1 : (kh == 1) ? cm1 : bm1;
            float v8  = (kh == 0) ? m8  : (kh == 1) ? c8  : b8;
            ull A0 = pk2(f0.x, f0.y), A1 = pk2(f0.z, f0.w), A2 = pk2(f1.x, f1.y), A3 = pk2(f1.z, f1.w);
            ull O0 = pk2(vm1, f0.x), O1 = pk2(f0.y, f0.z), O2 = pk2(f0.w, f1.x),
                O3 = pk2(f1.y, f1.z), O4 = pk2(f1.w, v8);
            const ull* wk = wp + kh * 9;
            #pragma unroll
            for (int oc = 0; oc < 3; oc++) {
                ull w0 = wk[oc], w1 = wk[3 + oc], w2 = wk[6 + oc];
                acc[oc*4+0] = ffma2(O0, w0, ffma2(A0, w1, ffma2(O1, w2, acc[oc*4+0])));
                acc[oc*4+1] = ffma2(O1, w0, ffma2(A1, w1, ffma2(O2, w2, acc[oc*4+1])));
                acc[oc*4+2] = ffma2(O2, w0, ffma2(A2, w1, ffma2(O3, w2, acc[oc*4+2])));
                acc[oc*4+3] = ffma2(O3, w0, ffma2(A3, w1, ffma2(O4, w2, acc[oc*4+3])));
            }
        }
    }

    const float* xp = x + (size_t)b * 3 * 65536 + oh * 256 + ow0;
    float sq = 0.f;
    #pragma unroll
    for (int oc = 0; oc < 3; oc++) {
        float4 x0 = *(const float4*)(xp + (size_t)oc * 65536);
        float4 x1 = *(const float4*)(xp + (size_t)oc * 65536 + 4);
        float2 p0 = upk2(acc[oc*4+0]), p1 = upk2(acc[oc*4+1]);
        float2 p2 = upk2(acc[oc*4+2]), p3 = upk2(acc[oc*4+3]);
        float e;
        e = p0.x - x0.x; sq = fmaf(e, e, sq);
        e = p0.y - x0.y; sq = fmaf(e, e, sq);
        e = p1.x - x0.z; sq = fmaf(e, e, sq);
        e = p1.y - x0.w; sq = fmaf(e, e, sq);
        e = p2.x - x1.x; sq = fmaf(e, e, sq);
        e = p2.y - x1.y; sq = fmaf(e, e, sq);
        e = p3.x - x1.z; sq = fmaf(e, e, sq);
        e = p3.y - x1.w; sq = fmaf(e, e, sq);
    }
    float bs = block_sum(sq, sred);
    if (threadIdx.x == 0) g_pmse[blockIdx.x] = bs;
}

// ---------------- deterministic final reduction ----------------
__global__ void k_final(float* __restrict__ out) {
    __shared__ double sd[256];
    double s1 = 0.0, s2 = 0.0;
    for (int i = threadIdx.x; i < 1024; i += 256) s1 += (double)g_pvq[i];
    for (int i = threadIdx.x; i < 2048; i += 256) s2 += (double)g_pmse[i];
    sd[threadIdx.x] = s1; __syncthreads();
    for (int o = 128; o > 0; o >>= 1) {
        if ((int)threadIdx.x < o) sd[threadIdx.x] += sd[threadIdx.x + o];
        __syncthreads();
    }
    double vq = sd[0]; __syncthreads();
    sd[threadIdx.x] = s2; __syncthreads();
    for (int o = 128; o > 0; o >>= 1) {
        if ((int)threadIdx.x < o) sd[threadIdx.x] += sd[threadIdx.x + o];
        __syncthreads();
    }
    if (threadIdx.x == 0) {
        double mq = vq / 4194304.0;                 // 64*64*64*16
        double mr = sd[0] / 12582912.0;             // 64*3*256*256
        out[0] = (float)(1.25 * mq);
        out[1] = (float)mr;
        out[2] = (float)mr;
    }
}

// ---------------- launch ----------------
extern "C" void kernel_launch(void* const* d_in, const int* in_sizes, int n_in,
                              void* d_out, int out_size) {
    const float* x   = (const float*)d_in[0];
    const float* ew1 = (const float*)d_in[1];
    const float* eb1 = (const float*)d_in[2];
    const float* ew2 = (const float*)d_in[3];
    const float* eb2 = (const float*)d_in[4];
    const float* ew3 = (const float*)d_in[5];
    const float* eb3 = (const float*)d_in[6];
    const float* cb  = (const float*)d_in[7];
    const float* dw1 = (const float*)d_in[8];
    const float* db1 = (const float*)d_in[9];
    const float* dw2 = (const float*)d_in[10];
    const float* db2 = (const float*)d_in[11];
    const float* dw3 = (const float*)d_in[12];
    const float* db3 = (const float*)d_in[13];
    float* out = (float*)d_out;

    const int smem_enc2 = 18432 * 4 + 64 * 8;  // 74240 B
    const int smem_dec1 = (6144 + 64) * 8;     // 49664 B
    const int smem_dec2 = (12288 + 32) * 8;    // 98560 B
    cudaFuncSetAttribute(k_enc2, cudaFuncAttributeMaxDynamicSharedMemorySize, smem_enc2);
    cudaFuncSetAttribute(k_dec1, cudaFuncAttributeMaxDynamicSharedMemorySize, smem_dec1);
    cudaFuncSetAttribute(k_dec2, cudaFuncAttributeMaxDynamicSharedMemorySize, smem_dec2);

    k_enc1    <<<4096, 256>>>(x, ew1, eb1);
    k_enc2    <<<1024, 256, smem_enc2>>>(ew2, eb2);
    k_enc3_vq <<<1024, 256>>>(ew3, eb3, cb);
    k_dec1    <<<4096, 256, smem_dec1>>>(dw1, db1);
    k_dec2    <<<8192, 256, smem_dec2>>>(dw2, db2);
    k_dec3_mse<<<2048, 256>>>(dw3, db3, x);
    k_final   <<<1, 256>>>(out);
}

// round 10
// speedup vs baseline: 1.8931x; 1.0347x over previous
#include <cuda_runtime.h>

typedef unsigned long long ull;

// ---------------- scratch (device globals; no allocation allowed) ----------------
static __device__ __align__(16) float g_a1[64*32*128*128];          // enc1 out
static __device__ __align__(16) float g_a2[64*64*64*64];            // enc2 out
static __device__ __align__(16) float g_q [64*16*64*64];            // quantized (decoder input)
static __device__ __align__(16) float g_d1[64*64*128*128];          // dec1 out
static __device__ __align__(16) float g_d2[64*32*256*256];          // dec2 out
static __device__ float g_pvq [1024];                               // per-block VQ sq-sum
static __device__ float g_pmse[2048];                               // per-block recon sq-sum

#define FULLMASK 0xffffffffu

// ---------------- f32x2 helpers ----------------
__device__ __forceinline__ ull pk2(float lo, float hi) {
    ull r;
    asm("mov.b64 %0, {%1, %2};" : "=l"(r)
        : "r"(__float_as_uint(lo)), "r"(__float_as_uint(hi)));
    return r;
}
__device__ __forceinline__ float2 upk2(ull p) {
    unsigned int a, b;
    asm("mov.b64 {%0, %1}, %2;" : "=r"(a), "=r"(b) : "l"(p));
    return make_float2(__uint_as_float(a), __uint_as_float(b));
}
__device__ __forceinline__ ull ffma2(ull a, ull b, ull c) {
    ull d;
    asm("fma.rn.f32x2 %0, %1, %2, %3;" : "=l"(d) : "l"(a), "l"(b), "l"(c));
    return d;
}
__device__ __forceinline__ float4 z4() { return make_float4(0.f, 0.f, 0.f, 0.f); }

// ---------------- reduction helper ----------------
__device__ __forceinline__ float block_sum(float v, float* sred) {
    int lane = threadIdx.x & 31, w = threadIdx.x >> 5;
    #pragma unroll
    for (int o = 16; o > 0; o >>= 1) v += __shfl_down_sync(FULLMASK, v, o);
    if (lane == 0) sred[w] = v;
    __syncthreads();
    if (w == 0) {
        v = (lane < (int)(blockDim.x >> 5)) ? sred[lane] : 0.f;
        #pragma unroll
        for (int o = 16; o > 0; o >>= 1) v += __shfl_down_sync(FULLMASK, v, o);
    }
    return v;  // valid in thread 0
}

#define FMA4(ACC, J, V, W4)                         \
    do {                                            \
        ACC[4*(J)+0] = fmaf(V, (W4).x, ACC[4*(J)+0]); \
        ACC[4*(J)+1] = fmaf(V, (W4).y, ACC[4*(J)+1]); \
        ACC[4*(J)+2] = fmaf(V, (W4).z, ACC[4*(J)+2]); \
        ACC[4*(J)+3] = fmaf(V, (W4).w, ACC[4*(J)+3]); \
    } while (0)

// transposed-conv tap: pair weights layout wq.x=(w1,w2) wq.y=(0,w0)
template <int C>
__device__ __forceinline__ void ctap(float4 f, float v4, const ull* wp, ull* acc) {
    ull d0 = pk2(f.x, f.x), d1 = pk2(f.y, f.y), d2 = pk2(f.z, f.z), d3 = pk2(f.w, f.w);
    ull o0 = pk2(f.x, f.y), o1 = pk2(f.y, f.z), o2 = pk2(f.z, f.w), o3 = pk2(f.w, v4);
    #pragma unroll
    for (int oc = 0; oc < C; oc++) {
        ulonglong2 wq = *(const ulonglong2*)(wp + oc * 2);
        acc[oc*4+0] = ffma2(d0, wq.x, ffma2(o0, wq.y, acc[oc*4+0]));
        acc[oc*4+1] = ffma2(d1, wq.x, ffma2(o1, wq.y, acc[oc*4+1]));
        acc[oc*4+2] = ffma2(d2, wq.x, ffma2(o2, wq.y, acc[oc*4+2]));
        acc[oc*4+3] = ffma2(d3, wq.x, ffma2(o3, wq.y, acc[oc*4+3]));
    }
}

// scalar-weight tap for enc2: weights are plain floats, dup'd at use
template <int C>
__device__ __forceinline__ void stap(ull P0, ull P1, ull P2, ull P3,
                                     const float* wp, ull* acc) {
    #pragma unroll
    for (int oc = 0; oc < C; oc += 4) {
        float4 wf = *(const float4*)(wp + oc);
        ull w;
        w = pk2(wf.x, wf.x);
        acc[(oc+0)*4+0] = ffma2(P0, w, acc[(oc+0)*4+0]);
        acc[(oc+0)*4+1] = ffma2(P1, w, acc[(oc+0)*4+1]);
        acc[(oc+0)*4+2] = ffma2(P2, w, acc[(oc+0)*4+2]);
        acc[(oc+0)*4+3] = ffma2(P3, w, acc[(oc+0)*4+3]);
        w = pk2(wf.y, wf.y);
        acc[(oc+1)*4+0] = ffma2(P0, w, acc[(oc+1)*4+0]);
        acc[(oc+1)*4+1] = ffma2(P1, w, acc[(oc+1)*4+1]);
        acc[(oc+1)*4+2] = ffma2(P2, w, acc[(oc+1)*4+2]);
        acc[(oc+1)*4+3] = ffma2(P3, w, acc[(oc+1)*4+3]);
        w = pk2(wf.z, wf.z);
        acc[(oc+2)*4+0] = ffma2(P0, w, acc[(oc+2)*4+0]);
        acc[(oc+2)*4+1] = ffma2(P1, w, acc[(oc+2)*4+1]);
        acc[(oc+2)*4+2] = ffma2(P2, w, acc[(oc+2)*4+2]);
        acc[(oc+2)*4+3] = ffma2(P3, w, acc[(oc+2)*4+3]);
        w = pk2(wf.w, wf.w);
        acc[(oc+3)*4+0] = ffma2(P0, w, acc[(oc+3)*4+0]);
        acc[(oc+3)*4+1] = ffma2(P1, w, acc[(oc+3)*4+1]);
        acc[(oc+3)*4+2] = ffma2(P2, w, acc[(oc+3)*4+2]);
        acc[(oc+3)*4+3] = ffma2(P3, w, acc[(oc+3)*4+3]);
    }
}

// ---------------- enc1: conv 3->32, k3 s2 p1, ReLU ----------------
__global__ void __launch_bounds__(256) k_enc1(const float* __restrict__ x,
                                              const float* __restrict__ w,
                                              const float* __restrict__ bias) {
    __shared__ __align__(16) float s_w[27 * 32];
    __shared__ float s_b[32];
    for (int i = threadIdx.x; i < 27 * 32; i += 256) {
        int oc = i & 31, t = i >> 5;
        s_w[i] = w[oc * 27 + t];
    }
    if (threadIdx.x < 32) s_b[threadIdx.x] = bias[threadIdx.x];
    __syncthreads();

    int tid = blockIdx.x * 256 + threadIdx.x;
    int ow = tid & 127, oh = (tid >> 7) & 127, b = tid >> 14;

    float acc[32];
    #pragma unroll
    for (int oc = 0; oc < 32; oc++) acc[oc] = s_b[oc];

    #pragma unroll
    for (int ic = 0; ic < 3; ic++) {
        const float* xp = x + (size_t)(b * 3 + ic) * 65536;
        #pragma unroll
        for (int kh = 0; kh < 3; kh++) {
            int ih = oh * 2 + kh - 1;
            if ((unsigned)ih >= 256u) continue;
            #pragma unroll
            for (int kw = 0; kw < 3; kw++) {
                int iw = ow * 2 + kw - 1;
                if ((unsigned)iw >= 256u) continue;
                float v = xp[ih * 256 + iw];
                const float4* wp = (const float4*)&s_w[(ic * 9 + kh * 3 + kw) * 32];
                #pragma unroll
                for (int j = 0; j < 8; j++) { float4 w4 = wp[j]; FMA4(acc, j, v, w4); }
            }
        }
    }
    float* op = g_a1 + (size_t)b * 32 * 16384 + oh * 128 + ow;
    #pragma unroll
    for (int oc = 0; oc < 32; oc++) op[oc * 16384] = fmaxf(acc[oc], 0.f);
}

// ---------------- enc2: conv 32->64, k3 s2 p1, ReLU (P=8, C=8, shfl halo) -----------
__global__ void __launch_bounds__(256, 2) k_enc2(const float* __restrict__ w,
                                                 const float* __restrict__ bias) {
    extern __shared__ __align__(16) float smf[];
    float* s_w = smf;                       // 18432 floats [kh][ic][kw][oc]
    ull* s_bd = (ull*)(smf + 18432);        // 64 pairs
    for (int i = threadIdx.x; i < 18432; i += 256) {
        int oc = i & 63; int t = i >> 6; int kw = t % 3; t /= 3; int ic = t & 31; int kh = t >> 5;
        s_w[i] = w[((oc * 32 + ic) * 3 + kh) * 3 + kw];
    }
    if (threadIdx.x < 64) { float bv = bias[threadIdx.x]; s_bd[threadIdx.x] = pk2(bv, bv); }
    __syncthreads();

    int tx = threadIdx.x;
    int chunk = tx & 7, ocg = (tx >> 3) & 7, r = tx >> 6;
    int b = blockIdx.x >> 4, rg = blockIdx.x & 15;
    int oh = rg * 4 + r;
    int ocb = ocg * 8;
    int ow0 = chunk * 8;

    ull acc[32];
    #pragma unroll
    for (int oc = 0; oc < 8; oc++) {
        ull bp = s_bd[ocb + oc];
        acc[oc*4+0] = bp; acc[oc*4+1] = bp; acc[oc*4+2] = bp; acc[oc*4+3] = bp;
    }

    #pragma unroll 1
    for (int ic = 0; ic < 32; ic++) {
        const float* plane = g_a1 + (size_t)(b * 32 + ic) * 16384;
        #pragma unroll
        for (int kh = 0; kh < 3; kh++) {
            int ih = 2 * oh + kh - 1;
            if ((unsigned)ih >= 128u) continue;
            const float* row = plane + ih * 128 + chunk * 16;
            float4 g0 = *(const float4*)row;
            float4 g1 = *(const float4*)(row + 4);
            float4 g2 = *(const float4*)(row + 8);
            float4 g3 = *(const float4*)(row + 12);
            float vm1 = __shfl_up_sync(FULLMASK, g3.w, 1);
            if (chunk == 0) vm1 = 0.f;
            const float* wp = s_w + ((kh * 32 + ic) * 3) * 64 + ocb;
            stap<8>(pk2(vm1,  g0.y), pk2(g0.w, g1.y), pk2(g1.w, g2.y), pk2(g2.w, g3.y), wp, acc);
            stap<8>(pk2(g0.x, g0.z), pk2(g1.x, g1.z), pk2(g2.x, g2.z), pk2(g3.x, g3.z), wp + 64, acc);
            stap<8>(pk2(g0.y, g0.w), pk2(g1.y, g1.w), pk2(g2.y, g2.w), pk2(g3.y, g3.w), wp + 128, acc);
        }
    }

    float* op = g_a2 + ((size_t)(b * 64 + ocb) * 64 + oh) * 64 + ow0;
    #pragma unroll
    for (int oc = 0; oc < 8; oc++) {
        float2 p0 = upk2(acc[oc*4+0]), p1 = upk2(acc[oc*4+1]);
        float2 p2 = upk2(acc[oc*4+2]), p3 = upk2(acc[oc*4+3]);
        float4 lo = make_float4(fmaxf(p0.x,0.f), fmaxf(p0.y,0.f), fmaxf(p1.x,0.f), fmaxf(p1.y,0.f));
        float4 hi = make_float4(fmaxf(p2.x,0.f), fmaxf(p2.y,0.f), fmaxf(p3.x,0.f), fmaxf(p3.y,0.f));
        *(float4*)(op + (size_t)oc * 4096) = lo;
        *(float4*)(op + (size_t)oc * 4096 + 4) = hi;
    }
}

// ---------------- enc3 (1x1, 64->16) + VQ + q-loss (unchanged) ----------------
__global__ void __launch_bounds__(256) k_enc3_vq(const float* __restrict__ w3,
                                                 const float* __restrict__ b3,
                                                 const float* __restrict__ cb) {
    __shared__ __align__(16) float s_w[64 * 16];
    __shared__ float s_b[16];
    __shared__ __align__(16) float s_cb[512 * 16];
    __shared__ float s_cn[512];
    __shared__ float sred[32];

    for (int i = threadIdx.x; i < 1024; i += 256) {
        int d = i & 15, ic = i >> 4;
        s_w[i] = w3[d * 64 + ic];
    }
    if (threadIdx.x < 16) s_b[threadIdx.x] = b3[threadIdx.x];
    for (int i = threadIdx.x; i < 8192; i += 256) s_cb[i] = cb[i];
    __syncthreads();
    for (int j = threadIdx.x; j < 512; j += 256) {
        float s = 0.f;
        #pragma unroll
        for (int d = 0; d < 16; d++) { float c = s_cb[j * 16 + d]; s = fmaf(c, c, s); }
        s_cn[j] = s;
    }
    __syncthreads();

    int tid = blockIdx.x * 256 + threadIdx.x;
    int p = tid & 4095, b = tid >> 12;

    float z[16];
    #pragma unroll
    for (int d = 0; d < 16; d++) z[d] = s_b[d];
    const float* ap = g_a2 + (size_t)b * 64 * 4096 + p;
    #pragma unroll 8
    for (int ic = 0; ic < 64; ic++) {
        float v = ap[ic * 4096];
        const float4* wp = (const float4*)&s_w[ic * 16];
        #pragma unroll
        for (int j = 0; j < 4; j++) { float4 w4 = wp[j]; FMA4(z, j, v, w4); }
    }

    int best = 0; float bd = 3.4e38f;
    for (int j = 0; j < 512; j++) {
        const float4* cp = (const float4*)&s_cb[j * 16];
        float dot = 0.f;
        #pragma unroll
        for (int q4 = 0; q4 < 4; q4++) {
            float4 c4 = cp[q4];
            dot = fmaf(z[4*q4+0], c4.x, dot);
            dot = fmaf(z[4*q4+1], c4.y, dot);
            dot = fmaf(z[4*q4+2], c4.z, dot);
            dot = fmaf(z[4*q4+3], c4.w, dot);
        }
        float dist = s_cn[j] - 2.f * dot;
        if (dist < bd) { bd = dist; best = j; }
    }

    float sq = 0.f;
    float* qp = g_q + (size_t)b * 16 * 4096 + p;
    #pragma unroll
    for (int d = 0; d < 16; d++) {
        float qv = s_cb[best * 16 + d];
        float df = qv - z[d];
        sq = fmaf(df, df, sq);
        qp[d * 4096] = qv;
    }
    float bs = block_sum(sq, sred);
    if (threadIdx.x == 0) g_pvq[blockIdx.x] = bs;
}

// ---------------- dec1: convT 16->64 k3 s2 p1 op1, ReLU (shfl halo, unroll4) ---------
// block: chunk(16) x ocg(8) x r(2) = 256. grid: 64b * 2ph * 32rg = 4096.
__global__ void __launch_bounds__(256, 2) k_dec1(const float* __restrict__ w,
                                                 const float* __restrict__ bias) {
    extern __shared__ __align__(16) ull smu[];
    ull* s_w = smu;               // 6144: [kh][ic][oc] -> {(w1,w2),(0,w0)}
    ull* s_bd = smu + 6144;       // 64
    for (int i = threadIdx.x; i < 6144; i += 256) {
        int h = i & 1; int t = i >> 1; int oc = t & 63; int t2 = t >> 6; int ic = t2 & 15; int kh = t2 >> 4;
        const float* wb = w + ((ic * 64 + oc) * 3 + kh) * 3;   // dec_w1 [16][64][3][3]
        s_w[i] = h ? pk2(0.f, wb[0]) : pk2(wb[1], wb[2]);
    }
    if (threadIdx.x < 64) { float bv = bias[threadIdx.x]; s_bd[threadIdx.x] = pk2(bv, bv); }
    __syncthreads();

    int tx = threadIdx.x;
    int chunk = tx & 15, ocg = (tx >> 4) & 7, r = tx >> 7;
    int bi = blockIdx.x;
    int b = bi >> 6; int rem = bi & 63; int ph = rem >> 5; int rg = rem & 31;
    int R = rg * 2 + r;
    int oh = 2 * R + ph;
    int ocb = ocg * 8;
    int ow0 = chunk * 8;

    ull acc[32];
    #pragma unroll
    for (int oc = 0; oc < 8; oc++) {
        ull bp = s_bd[ocb + oc];
        acc[oc*4+0] = bp; acc[oc*4+1] = bp; acc[oc*4+2] = bp; acc[oc*4+3] = bp;
    }

    const float* base = g_q + (size_t)b * 16 * 4096 + chunk * 4;
    bool edge = (chunk < 15);

    if (ph == 0) {                 // single tap kh=1 @ row R; ic-unroll 4 (MLP=4)
        const float* p0 = base + R * 64;
        #pragma unroll 1
        for (int ic = 0; ic < 16; ic += 4) {
            float4 f0 = *(const float4*)(p0 + (ic + 0) * 4096);
            float4 f1 = *(const float4*)(p0 + (ic + 1) * 4096);
            float4 f2 = *(const float4*)(p0 + (ic + 2) * 4096);
            float4 f3 = *(const float4*)(p0 + (ic + 3) * 4096);
            float v0 = __shfl_down_sync(FULLMASK, f0.x, 1); if (!edge) v0 = 0.f;
            float v1 = __shfl_down_sync(FULLMASK, f1.x, 1); if (!edge) v1 = 0.f;
            float v2 = __shfl_down_sync(FULLMASK, f2.x, 1); if (!edge) v2 = 0.f;
            float v3 = __shfl_down_sync(FULLMASK, f3.x, 1); if (!edge) v3 = 0.f;
            ctap<8>(f0, v0, s_w + ((1 * 16 + ic + 0) * 64 + ocb) * 2, acc);
            ctap<8>(f1, v1, s_w + ((1 * 16 + ic + 1) * 64 + ocb) * 2, acc);
            ctap<8>(f2, v2, s_w + ((1 * 16 + ic + 2) * 64 + ocb) * 2, acc);
            ctap<8>(f3, v3, s_w + ((1 * 16 + ic + 3) * 64 + ocb) * 2, acc);
        }
    } else {                       // taps kh=2 @ R, kh=0 @ R+1; ic-unroll 2 (MLP=4)
        bool ok = (R + 1 < 64);
        const float* pa = base + R * 64;
        const float* pb = base + (R + 1) * 64;
        #pragma unroll 1
        for (int ic = 0; ic < 16; ic += 2) {
            float4 fa0 = *(const float4*)(pa + ic * 4096);
            float4 fa1 = *(const float4*)(pa + (ic + 1) * 4096);
            float4 fb0 = ok ? *(const float4*)(pb + ic * 4096) : z4();
            float4 fb1 = ok ? *(const float4*)(pb + (ic + 1) * 4096) : z4();
            float va0 = __shfl_down_sync(FULLMASK, fa0.x, 1); if (!edge) va0 = 0.f;
            float va1 = __shfl_down_sync(FULLMASK, fa1.x, 1); if (!edge) va1 = 0.f;
            float vb0 = __shfl_down_sync(FULLMASK, fb0.x, 1); if (!edge) vb0 = 0.f;
            float vb1 = __shfl_down_sync(FULLMASK, fb1.x, 1); if (!edge) vb1 = 0.f;
            ctap<8>(fa0, va0, s_w + ((2 * 16 + ic)     * 64 + ocb) * 2, acc);
            ctap<8>(fb0, vb0, s_w + ((0 * 16 + ic)     * 64 + ocb) * 2, acc);
            ctap<8>(fa1, va1, s_w + ((2 * 16 + ic + 1) * 64 + ocb) * 2, acc);
            ctap<8>(fb1, vb1, s_w + ((0 * 16 + ic + 1) * 64 + ocb) * 2, acc);
        }
    }

    float* op = g_d1 + ((size_t)(b * 64 + ocb) * 128 + oh) * 128 + ow0;
    #pragma unroll
    for (int oc = 0; oc < 8; oc++) {
        float2 p0 = upk2(acc[oc*4+0]), p1 = upk2(acc[oc*4+1]);
        float2 p2 = upk2(acc[oc*4+2]), p3 = upk2(acc[oc*4+3]);
        float4 lo = make_float4(fmaxf(p0.x,0.f), fmaxf(p0.y,0.f), fmaxf(p1.x,0.f), fmaxf(p1.y,0.f));
        float4 hi = make_float4(fmaxf(p2.x,0.f), fmaxf(p2.y,0.f), fmaxf(p3.x,0.f), fmaxf(p3.y,0.f));
        *(float4*)(op + (size_t)oc * 16384) = lo;
        *(float4*)(op + (size_t)oc * 16384 + 4) = hi;
    }
}

// ---------------- dec2: convT 64->32 k3 s2 p1 op1, ReLU (shfl halo, unroll4) ---------
// block: chunk(32) x ocg(4) x r(2) = 256. grid: 64b * 2ph * 64rg = 8192.
__global__ void __launch_bounds__(256, 2) k_dec2(const float* __restrict__ w,
                                                 const float* __restrict__ bias) {
    extern __shared__ __align__(16) ull smu[];
    ull* s_w = smu;                // 12288: [kh][ic][oc] pairs
    ull* s_bd = smu + 12288;       // 32
    for (int i = threadIdx.x; i < 12288; i += 256) {
        int h = i & 1; int t = i >> 1; int oc = t & 31; int t2 = t >> 5; int ic = t2 & 63; int kh = t2 >> 6;
        const float* wb = w + ((ic * 32 + oc) * 3 + kh) * 3;   // dec_w2 [64][32][3][3]
        s_w[i] = h ? pk2(0.f, wb[0]) : pk2(wb[1], wb[2]);
    }
    if (threadIdx.x < 32) { float bv = bias[threadIdx.x]; s_bd[threadIdx.x] = pk2(bv, bv); }
    __syncthreads();

    int tx = threadIdx.x;
    int chunk = tx & 31, ocg = (tx >> 5) & 3, r = tx >> 7;
    int bi = blockIdx.x;
    int b = bi >> 7; int rem = bi & 127; int ph = rem >> 6; int rg = rem & 63;
    int R = rg * 2 + r;
    int oh = 2 * R + ph;
    int ocb = ocg * 8;
    int ow0 = chunk * 8;

    ull acc[32];
    #pragma unroll
    for (int oc = 0; oc < 8; oc++) {
        ull bp = s_bd[ocb + oc];
        acc[oc*4+0] = bp; acc[oc*4+1] = bp; acc[oc*4+2] = bp; acc[oc*4+3] = bp;
    }

    const float* base = g_d1 + (size_t)b * 64 * 16384 + chunk * 4;
    bool edge = (chunk < 31);

    if (ph == 0) {                 // single tap kh=1 @ row R; ic-unroll 4 (MLP=4)
        const float* p0 = base + R * 128;
        #pragma unroll 1
        for (int ic = 0; ic < 64; ic += 4) {
            float4 f0 = *(const float4*)(p0 + (size_t)(ic + 0) * 16384);
            float4 f1 = *(const float4*)(p0 + (size_t)(ic + 1) * 16384);
            float4 f2 = *(const float4*)(p0 + (size_t)(ic + 2) * 16384);
            float4 f3 = *(const float4*)(p0 + (size_t)(ic + 3) * 16384);
            float v0 = __shfl_down_sync(FULLMASK, f0.x, 1); if (!edge) v0 = 0.f;
            float v1 = __shfl_down_sync(FULLMASK, f1.x, 1); if (!edge) v1 = 0.f;
            float v2 = __shfl_down_sync(FULLMASK, f2.x, 1); if (!edge) v2 = 0.f;
            float v3 = __shfl_down_sync(FULLMASK, f3.x, 1); if (!edge) v3 = 0.f;
            ctap<8>(f0, v0, s_w + ((1 * 64 + ic + 0) * 32 + ocb) * 2, acc);
            ctap<8>(f1, v1, s_w + ((1 * 64 + ic + 1) * 32 + ocb) * 2, acc);
            ctap<8>(f2, v2, s_w + ((1 * 64 + ic + 2) * 32 + ocb) * 2, acc);
            ctap<8>(f3, v3, s_w + ((1 * 64 + ic + 3) * 32 + ocb) * 2, acc);
        }
    } else {                       // taps kh=2 @ R, kh=0 @ R+1; ic-unroll 2 (MLP=4)
        bool ok = (R + 1 < 128);
        const float* pa = base + R * 128;
        const float* pb = base + (R + 1) * 128;
        #pragma unroll 1
        for (int ic = 0; ic < 64; ic += 2) {
            float4 fa0 = *(const float4*)(pa + (size_t)ic * 16384);
            float4 fa1 = *(const float4*)(pa + (size_t)(ic + 1) * 16384);
            float4 fb0 = ok ? *(const float4*)(pb + (size_t)ic * 16384) : z4();
            float4 fb1 = ok ? *(const float4*)(pb + (size_t)(ic + 1) * 16384) : z4();
            float va0 = __shfl_down_sync(FULLMASK, fa0.x, 1); if (!edge) va0 = 0.f;
            float va1 = __shfl_down_sync(FULLMASK, fa1.x, 1); if (!edge) va1 = 0.f;
            float vb0 = __shfl_down_sync(FULLMASK, fb0.x, 1); if (!edge) vb0 = 0.f;
            float vb1 = __shfl_down_sync(FULLMASK, fb1.x, 1); if (!edge) vb1 = 0.f;
            ctap<8>(fa0, va0, s_w + ((2 * 64 + ic)     * 32 + ocb) * 2, acc);
            ctap<8>(fb0, vb0, s_w + ((0 * 64 + ic)     * 32 + ocb) * 2, acc);
            ctap<8>(fa1, va1, s_w + ((2 * 64 + ic + 1) * 32 + ocb) * 2, acc);
            ctap<8>(fb1, vb1, s_w + ((0 * 64 + ic + 1) * 32 + ocb) * 2, acc);
        }
    }

    float* op = g_d2 + ((size_t)(b * 32 + ocb) * 256 + oh) * 256 + ow0;
    #pragma unroll
    for (int oc = 0; oc < 8; oc++) {
        float2 p0 = upk2(acc[oc*4+0]), p1 = upk2(acc[oc*4+1]);
        float2 p2 = upk2(acc[oc*4+2]), p3 = upk2(acc[oc*4+3]);
        float4 lo = make_float4(fmaxf(p0.x,0.f), fmaxf(p0.y,0.f), fmaxf(p1.x,0.f), fmaxf(p1.y,0.f));
        float4 hi = make_float4(fmaxf(p2.x,0.f), fmaxf(p2.y,0.f), fmaxf(p3.x,0.f), fmaxf(p3.y,0.f));
        *(float4*)(op + (size_t)oc * 65536) = lo;
        *(float4*)(op + (size_t)oc * 65536 + 4) = hi;
    }
}

// ---------------- dec3: convT 32->3 s1 p1 + fused MSE (shfl halo, MLP=6) -------------
__global__ void __launch_bounds__(256) k_dec3_mse(const float* __restrict__ w,
                                                  const float* __restrict__ bias,
                                                  const float* __restrict__ x) {
    __shared__ __align__(16) ull s_wd[864];   // [ic][kh][kw][oc] dup pairs
    __shared__ ull s_bd[3];
    __shared__ float sred[32];
    for (int i = threadIdx.x; i < 864; i += 256) {
        int oc = i % 3; int t = i / 3; int kw = t % 3; t /= 3; int kh = t % 3; int ic = t / 3;
        float wv = w[ic * 27 + oc * 9 + (2 - kh) * 3 + (2 - kw)];   // dec_w3 flipped
        s_wd[i] = pk2(wv, wv);
    }
    if (threadIdx.x < 3) { float bv = bias[threadIdx.x]; s_bd[threadIdx.x] = pk2(bv, bv); }
    __syncthreads();

    int tx = threadIdx.x;
    int chunk = tx & 31, r = tx >> 5;
    int b = blockIdx.x >> 5, rg = blockIdx.x & 31;
    int oh = rg * 8 + r;
    int ow0 = chunk * 8;

    bool ok0 = (oh > 0), ok2 = (oh < 255);
    bool eL = (chunk != 0), eR = (chunk != 31);

    ull acc[12];
    #pragma unroll
    for (int oc = 0; oc < 3; oc++) {
        ull bp = s_bd[oc];
        acc[oc*4+0] = bp; acc[oc*4+1] = bp; acc[oc*4+2] = bp; acc[oc*4+3] = bp;
    }

    #pragma unroll 1
    for (int ic = 0; ic < 32; ic++) {
        const float* rowm = g_d2 + (size_t)(b * 32 + ic) * 65536 + (oh - 1) * 256 + ow0;
        float4 m0 = ok0 ? *(const float4*)rowm       : z4();
        float4 m1 = ok0 ? *(const float4*)(rowm + 4) : z4();
        float4 c0 = *(const float4*)(rowm + 256);
        float4 c1 = *(const float4*)(rowm + 260);
        float4 b0 = ok2 ? *(const float4*)(rowm + 512) : z4();
        float4 b1 = ok2 ? *(const float4*)(rowm + 516) : z4();
        float mm1 = __shfl_up_sync(FULLMASK, m1.w, 1);   if (!eL) mm1 = 0.f;
        float cm1 = __shfl_up_sync(FULLMASK, c1.w, 1);   if (!eL) cm1 = 0.f;
        float bm1 = __shfl_up_sync(FULLMASK, b1.w, 1);   if (!eL) bm1 = 0.f;
        float m8  = __shfl_down_sync(FULLMASK, m0.x, 1); if (!eR) m8 = 0.f;
        float c8  = __shfl_down_sync(FULLMASK, c0.x, 1); if (!eR) c8 = 0.f;
        float b8  = __shfl_down_sync(FULLMASK, b0.x, 1); if (!eR) b8 = 0.f;

        const ull* wp = s_wd + ic * 27;   // [kh][kw][oc]
        #pragma unroll
        for (int kh = 0; kh < 3; kh++) {
            float4 f0 = (kh == 0) ? m0 : (kh == 1) ? c0 : b0;
            float4 f1 = (kh == 0) ? m1 : (kh == 1) ? c1 : b1;
            float vm1 = (kh == 0) ? mm1 : (kh == 1) ? cm1 : bm1;
            float v8  = (kh == 0) ? m8  : (kh == 1) ? c8  : b8;
            ull A0 = pk2(f0.x, f0.y), A1 = pk2(f0.z, f0.w), A2 = pk2(f1.x, f1.y), A3 = pk2(f1.z, f1.w);
            ull O0 = pk2(vm1, f0.x), O1 = pk2(f0.y, f0.z), O2 = pk2(f0.w, f1.x),
                O3 = pk2(f1.y, f1.z), O4 = pk2(f1.w, v8);
            const ull* wk = wp + kh * 9;
            #pragma unroll
            for (int oc = 0; oc < 3; oc++) {
                ull w0 = wk[oc], w1 = wk[3 + oc], w2 = wk[6 + oc];
                acc[oc*4+0] = ffma2(O0, w0, ffma2(A0, w1, ffma2(O1, w2, acc[oc*4+0])));
                acc[oc*4+1] = ffma2(O1, w0, ffma2(A1, w1, ffma2(O2, w2, acc[oc*4+1])));
                acc[oc*4+2] = ffma2(O2, w0, ffma2(A2, w1, ffma2(O3, w2, acc[oc*4+2])));
                acc[oc*4+3] = ffma2(O3, w0, ffma2(A3, w1, ffma2(O4, w2, acc[oc*4+3])));
            }
        }
    }

    const float* xp = x + (size_t)b * 3 * 65536 + oh * 256 + ow0;
    float sq = 0.f;
    #pragma unroll
    for (int oc = 0; oc < 3; oc++) {
        float4 x0 = *(const float4*)(xp + (size_t)oc * 65536);
        float4 x1 = *(const float4*)(xp + (size_t)oc * 65536 + 4);
        float2 p0 = upk2(acc[oc*4+0]), p1 = upk2(acc[oc*4+1]);
        float2 p2 = upk2(acc[oc*4+2]), p3 = upk2(acc[oc*4+3]);
        float e;
        e = p0.x - x0.x; sq = fmaf(e, e, sq);
        e = p0.y - x0.y; sq = fmaf(e, e, sq);
        e = p1.x - x0.z; sq = fmaf(e, e, sq);
        e = p1.y - x0.w; sq = fmaf(e, e, sq);
        e = p2.x - x1.x; sq = fmaf(e, e, sq);
        e = p2.y - x1.y; sq = fmaf(e, e, sq);
        e = p3.x - x1.z; sq = fmaf(e, e, sq);
        e = p3.y - x1.w; sq = fmaf(e, e, sq);
    }
    float bs = block_sum(sq, sred);
    if (threadIdx.x == 0) g_pmse[blockIdx.x] = bs;
}

// ---------------- deterministic final reduction ----------------
__global__ void k_final(float* __restrict__ out) {
    __shared__ double sd[256];
    double s1 = 0.0, s2 = 0.0;
    for (int i = threadIdx.x; i < 1024; i += 256) s1 += (double)g_pvq[i];
    for (int i = threadIdx.x; i < 2048; i += 256) s2 += (double)g_pmse[i];
    sd[threadIdx.x] = s1; __syncthreads();
    for (int o = 128; o > 0; o >>= 1) {
        if ((int)threadIdx.x < o) sd[threadIdx.x] += sd[threadIdx.x + o];
        __syncthreads();
    }
    double vq = sd[0]; __syncthreads();
    sd[threadIdx.x] = s2; __syncthreads();
    for (int o = 128; o > 0; o >>= 1) {
        if ((int)threadIdx.x < o) sd[threadIdx.x] += sd[threadIdx.x + o];
        __syncthreads();
    }
    if (threadIdx.x == 0) {
        double mq = vq / 4194304.0;                 // 64*64*64*16
        double mr = sd[0] / 12582912.0;             // 64*3*256*256
        out[0] = (float)(1.25 * mq);
        out[1] = (float)mr;
        out[2] = (float)mr;
    }
}

// ---------------- launch ----------------
extern "C" void kernel_launch(void* const* d_in, const int* in_sizes, int n_in,
                              void* d_out, int out_size) {
    const float* x   = (const float*)d_in[0];
    const float* ew1 = (const float*)d_in[1];
    const float* eb1 = (const float*)d_in[2];
    const float* ew2 = (const float*)d_in[3];
    const float* eb2 = (const float*)d_in[4];
    const float* ew3 = (const float*)d_in[5];
    const float* eb3 = (const float*)d_in[6];
    const float* cb  = (const float*)d_in[7];
    const float* dw1 = (const float*)d_in[8];
    const float* db1 = (const float*)d_in[9];
    const float* dw2 = (const float*)d_in[10];
    const float* db2 = (const float*)d_in[11];
    const float* dw3 = (const float*)d_in[12];
    const float* db3 = (const float*)d_in[13];
    float* out = (float*)d_out;

    const int smem_enc2 = 18432 * 4 + 64 * 8;  // 74240 B
    const int smem_dec1 = (6144 + 64) * 8;     // 49664 B
    const int smem_dec2 = (12288 + 32) * 8;    // 98560 B
    cudaFuncSetAttribute(k_enc2, cudaFuncAttributeMaxDynamicSharedMemorySize, smem_enc2);
    cudaFuncSetAttribute(k_dec1, cudaFuncAttributeMaxDynamicSharedMemorySize, smem_dec1);
    cudaFuncSetAttribute(k_dec2, cudaFuncAttributeMaxDynamicSharedMemorySize, smem_dec2);

    k_enc1    <<<4096, 256>>>(x, ew1, eb1);
    k_enc2    <<<1024, 256, smem_enc2>>>(ew2, eb2);
    k_enc3_vq <<<1024, 256>>>(ew3, eb3, cb);
    k_dec1    <<<4096, 256, smem_dec1>>>(dw1, db1);
    k_dec2    <<<8192, 256, smem_dec2>>>(dw2, db2);
    k_dec3_mse<<<2048, 256>>>(dw3, db3, x);
    k_final   <<<1, 256>>>(out);
}

// round 11
// speedup vs baseline: 2.3906x; 1.2628x over previous
#include <cuda_runtime.h>

typedef unsigned long long ull;

// ---------------- scratch (device globals; no allocation allowed) ----------------
static __device__ __align__(16) float g_a1[64*32*128*128];          // enc1 out
static __device__ __align__(16) float g_a2[64*64*64*64];            // enc2 out
static __device__ __align__(16) float g_q [64*16*64*64];            // quantized (decoder input)
static __device__ __align__(16) float g_d1[64*64*128*128];          // dec1 out
static __device__ __align__(16) float g_d2[64*32*256*256];          // dec2 out
static __device__ float g_pvq [1024];                               // per-block VQ sq-sum
static __device__ float g_pmse[2048];                               // per-block recon sq-sum

#define FULLMASK 0xffffffffu

// ---------------- f32x2 helpers ----------------
__device__ __forceinline__ ull pk2(float lo, float hi) {
    ull r;
    asm("mov.b64 %0, {%1, %2};" : "=l"(r)
        : "r"(__float_as_uint(lo)), "r"(__float_as_uint(hi)));
    return r;
}
__device__ __forceinline__ float2 upk2(ull p) {
    unsigned int a, b;
    asm("mov.b64 {%0, %1}, %2;" : "=r"(a), "=r"(b) : "l"(p));
    return make_float2(__uint_as_float(a), __uint_as_float(b));
}
__device__ __forceinline__ ull ffma2(ull a, ull b, ull c) {
    ull d;
    asm("fma.rn.f32x2 %0, %1, %2, %3;" : "=l"(d) : "l"(a), "l"(b), "l"(c));
    return d;
}
__device__ __forceinline__ float4 z4() { return make_float4(0.f, 0.f, 0.f, 0.f); }
__device__ __forceinline__ float rl(float v) { return fmaxf(v, 0.f); }

// ---------------- reduction helper ----------------
__device__ __forceinline__ float block_sum(float v, float* sred) {
    int lane = threadIdx.x & 31, w = threadIdx.x >> 5;
    #pragma unroll
    for (int o = 16; o > 0; o >>= 1) v += __shfl_down_sync(FULLMASK, v, o);
    if (lane == 0) sred[w] = v;
    __syncthreads();
    if (w == 0) {
        v = (lane < (int)(blockDim.x >> 5)) ? sred[lane] : 0.f;
        #pragma unroll
        for (int o = 16; o > 0; o >>= 1) v += __shfl_down_sync(FULLMASK, v, o);
    }
    return v;  // valid in thread 0
}

#define FMA4(ACC, J, V, W4)                         \
    do {                                            \
        ACC[4*(J)+0] = fmaf(V, (W4).x, ACC[4*(J)+0]); \
        ACC[4*(J)+1] = fmaf(V, (W4).y, ACC[4*(J)+1]); \
        ACC[4*(J)+2] = fmaf(V, (W4).z, ACC[4*(J)+2]); \
        ACC[4*(J)+3] = fmaf(V, (W4).w, ACC[4*(J)+3]); \
    } while (0)

// transposed-conv tap, oc-pair packing. Even outputs: w1*v_j. Odd: w2*v_j + w0*v_{j+1}.
// Weight pairs (w_oc0, w_oc1) preloaded in smem; multiplicands are dup pairs (v,v).
__device__ __forceinline__ void ptap(float4 f, float v4,
                                     const ull* w1p, const ull* w2p, const ull* w0p,
                                     ull* ae, ull* ao) {
    ull d0 = pk2(f.x, f.x), d1 = pk2(f.y, f.y), d2 = pk2(f.z, f.z), d3 = pk2(f.w, f.w);
    ull d4 = pk2(v4, v4);
    ulonglong2 A = *(const ulonglong2*)w1p, B = *(const ulonglong2*)(w1p + 2);
    ulonglong2 C = *(const ulonglong2*)w2p, D = *(const ulonglong2*)(w2p + 2);
    ulonglong2 E = *(const ulonglong2*)w0p, F = *(const ulonglong2*)(w0p + 2);
    ull W1[4] = {A.x, A.y, B.x, B.y};
    ull W2[4] = {C.x, C.y, D.x, D.y};
    ull W0[4] = {E.x, E.y, F.x, F.y};
    #pragma unroll
    for (int p = 0; p < 4; p++) {
        ae[0*4+p] = ffma2(d0, W1[p], ae[0*4+p]);
        ae[1*4+p] = ffma2(d1, W1[p], ae[1*4+p]);
        ae[2*4+p] = ffma2(d2, W1[p], ae[2*4+p]);
        ae[3*4+p] = ffma2(d3, W1[p], ae[3*4+p]);
        ao[0*4+p] = ffma2(d1, W0[p], ffma2(d0, W2[p], ao[0*4+p]));
        ao[1*4+p] = ffma2(d2, W0[p], ffma2(d1, W2[p], ao[1*4+p]));
        ao[2*4+p] = ffma2(d3, W0[p], ffma2(d2, W2[p], ao[2*4+p]));
        ao[3*4+p] = ffma2(d4, W0[p], ffma2(d3, W2[p], ao[3*4+p]));
    }
}

// ---------------- enc1: conv 3->32, k3 s2 p1, ReLU (P=2 px, oc-pair) ----------------
// thread: pixel pair (2j, 2j+1) of row oh; all 32 oc as 16 oc-pairs. grid 2048x256.
__global__ void __launch_bounds__(256) k_enc1(const float* __restrict__ x,
                                              const float* __restrict__ w,
                                              const float* __restrict__ bias) {
    __shared__ __align__(16) ull s_wp[432];   // [t = ic*9+kh*3+kw][16 ocp]
    __shared__ ull s_bd[16];
    for (int i = threadIdx.x; i < 432; i += 256) {
        int ocp = i & 15, t = i >> 4;
        s_wp[i] = pk2(w[(2 * ocp) * 27 + t], w[(2 * ocp + 1) * 27 + t]);
    }
    if (threadIdx.x < 16) s_bd[threadIdx.x] = pk2(bias[2*threadIdx.x], bias[2*threadIdx.x+1]);
    __syncthreads();

    int tid = blockIdx.x * 256 + threadIdx.x;      // 64*128*64 threads
    int j = tid & 63, oh = (tid >> 6) & 127, b = tid >> 13;
    int lane = threadIdx.x & 31;

    ull a0[16], a1[16];
    #pragma unroll
    for (int p = 0; p < 16; p++) { a0[p] = s_bd[p]; a1[p] = s_bd[p]; }

    #pragma unroll
    for (int ic = 0; ic < 3; ic++) {
        const float* xp = x + (size_t)(b * 3 + ic) * 65536;
        #pragma unroll
        for (int kh = 0; kh < 3; kh++) {
            int ih = 2 * oh + kh - 1;
            bool okh = (unsigned)ih < 256u;
            const float* row = xp + ih * 256 + 4 * j;
            float4 f = okh ? *(const float4*)row : z4();
            float vL = __shfl_up_sync(FULLMASK, f.w, 1);
            if (lane == 0) vL = (okh && j > 0) ? row[-1] : 0.f;
            // out[2j]  : kw0->in[4j-1]=vL, kw1->f.x, kw2->f.y
            // out[2j+1]: kw0->f.y,          kw1->f.z, kw2->f.w
            ull dL = pk2(vL, vL), dx = pk2(f.x, f.x), dy = pk2(f.y, f.y);
            ull dz = pk2(f.z, f.z), dw_ = pk2(f.w, f.w);
            const ull* wb = s_wp + (ic * 9 + kh * 3) * 16;
            #pragma unroll
            for (int kw = 0; kw < 3; kw++) {
                ull da = (kw == 0) ? dL : (kw == 1) ? dx : dy;
                ull db = (kw == 0) ? dy : (kw == 1) ? dz : dw_;
                const ull* wk = wb + kw * 16;
                #pragma unroll
                for (int p = 0; p < 16; p += 2) {
                    ulonglong2 wp2 = *(const ulonglong2*)(wk + p);
                    a0[p]     = ffma2(da, wp2.x, a0[p]);
                    a0[p + 1] = ffma2(da, wp2.y, a0[p + 1]);
                    a1[p]     = ffma2(db, wp2.x, a1[p]);
                    a1[p + 1] = ffma2(db, wp2.y, a1[p + 1]);
                }
            }
        }
    }
    float* op = g_a1 + (size_t)b * 32 * 16384 + oh * 128 + 2 * j;
    #pragma unroll
    for (int p = 0; p < 16; p++) {
        float2 v0 = upk2(a0[p]);   // (oc=2p px0, oc=2p+1 px0)
        float2 v1 = upk2(a1[p]);   // px1
        float2 e;
        e.x = rl(v0.x); e.y = rl(v1.x); *(float2*)(op + (size_t)(2*p)   * 16384) = e;
        e.x = rl(v0.y); e.y = rl(v1.y); *(float2*)(op + (size_t)(2*p+1) * 16384) = e;
    }
}

// ---------------- enc2: conv 32->64, k3 s2 p1, ReLU (P=8, oc-pair, RR=2) ------------
// block: chunk(8) x ocg(8) x r(4) = 256. grid: 64b * 8 rowgroups = 512.
__global__ void __launch_bounds__(256, 2) k_enc2(const float* __restrict__ w,
                                                 const float* __restrict__ bias) {
    extern __shared__ __align__(16) ull smu[];
    ull* s_w = smu;               // 9216: [kh][ic][kw][32 ocp] oc-pairs
    ull* s_bd = smu + 9216;       // 32
    for (int i = threadIdx.x; i < 9216; i += 256) {
        int ocp = i & 31; int q = i >> 5; int kw = q % 3; int t2 = q / 3;
        int ic = t2 & 31; int kh = t2 >> 5;
        s_w[i] = pk2(w[(2*ocp)     * 288 + ic * 9 + kh * 3 + kw],
                     w[(2*ocp + 1) * 288 + ic * 9 + kh * 3 + kw]);
    }
    if (threadIdx.x < 32) s_bd[threadIdx.x] = pk2(bias[2*threadIdx.x], bias[2*threadIdx.x+1]);
    __syncthreads();

    int tx = threadIdx.x;
    int chunk = tx & 7, ocg = (tx >> 3) & 7, r = tx >> 6;
    int b = blockIdx.x >> 3, rg = blockIdx.x & 7;
    int ocp0 = ocg * 4;
    int ow0 = chunk * 8;

    #pragma unroll 1
    for (int rr = 0; rr < 2; rr++) {
        int oh = rg * 8 + rr * 4 + r;

        ull acc[32];   // [owl][p]
        #pragma unroll
        for (int p = 0; p < 4; p++) {
            ull bp = s_bd[ocp0 + p];
            #pragma unroll
            for (int owl = 0; owl < 8; owl++) acc[owl*4+p] = bp;
        }

        #pragma unroll 1
        for (int ic = 0; ic < 32; ic++) {
            const float* plane = g_a1 + (size_t)(b * 32 + ic) * 16384;
            #pragma unroll
            for (int kh = 0; kh < 3; kh++) {
                int ih = 2 * oh + kh - 1;
                if ((unsigned)ih >= 128u) continue;
                const float* row = plane + ih * 128 + chunk * 16;
                float4 g0 = *(const float4*)row;
                float4 g1 = *(const float4*)(row + 4);
                float4 g2 = *(const float4*)(row + 8);
                float4 g3 = *(const float4*)(row + 12);
                float vm1 = __shfl_up_sync(FULLMASK, g3.w, 1);
                if (chunk == 0) vm1 = 0.f;
                const ull* wb = s_w + ((kh * 32 + ic) * 3) * 32 + ocp0;
                ulonglong2 wa0 = *(const ulonglong2*)(wb),      wb0 = *(const ulonglong2*)(wb + 2);
                ulonglong2 wa1 = *(const ulonglong2*)(wb + 32), wb1 = *(const ulonglong2*)(wb + 34);
                ulonglong2 wa2 = *(const ulonglong2*)(wb + 64), wb2 = *(const ulonglong2*)(wb + 66);
                ull W0[4] = {wa0.x, wa0.y, wb0.x, wb0.y};
                ull W1[4] = {wa1.x, wa1.y, wb1.x, wb1.y};
                ull W2[4] = {wa2.x, wa2.y, wb2.x, wb2.y};
                float s[17] = {vm1, g0.x, g0.y, g0.z, g0.w, g1.x, g1.y, g1.z, g1.w,
                               g2.x, g2.y, g2.z, g2.w, g3.x, g3.y, g3.z, g3.w};
                #pragma unroll
                for (int owl = 0; owl < 8; owl++) {
                    ull dA = pk2(s[2*owl],     s[2*owl]);
                    ull dB = pk2(s[2*owl + 1], s[2*owl + 1]);
                    ull dC = pk2(s[2*owl + 2], s[2*owl + 2]);
                    #pragma unroll
                    for (int p = 0; p < 4; p++)
                        acc[owl*4+p] = ffma2(dA, W0[p], ffma2(dB, W1[p], ffma2(dC, W2[p], acc[owl*4+p])));
                }
            }
        }

        float* op = g_a2 + ((size_t)(b * 64 + ocg * 8) * 64 + oh) * 64 + ow0;
        #pragma unroll
        for (int p = 0; p < 4; p++) {
            float2 q0 = upk2(acc[0*4+p]), q1 = upk2(acc[1*4+p]), q2 = upk2(acc[2*4+p]), q3 = upk2(acc[3*4+p]);
            float2 q4 = upk2(acc[4*4+p]), q5 = upk2(acc[5*4+p]), q6 = upk2(acc[6*4+p]), q7 = upk2(acc[7*4+p]);
            float* d0 = op + (size_t)(2*p) * 4096;
            float* d1 = d0 + 4096;
            *(float4*)d0       = make_float4(rl(q0.x), rl(q1.x), rl(q2.x), rl(q3.x));
            *(float4*)(d0 + 4) = make_float4(rl(q4.x), rl(q5.x), rl(q6.x), rl(q7.x));
            *(float4*)d1       = make_float4(rl(q0.y), rl(q1.y), rl(q2.y), rl(q3.y));
            *(float4*)(d1 + 4) = make_float4(rl(q4.y), rl(q5.y), rl(q6.y), rl(q7.y));
        }
    }
}

// ---------------- enc3 (1x1, 64->16) + VQ + q-loss (unchanged) ----------------
__global__ void __launch_bounds__(256) k_enc3_vq(const float* __restrict__ w3,
                                                 const float* __restrict__ b3,
                                                 const float* __restrict__ cb) {
    __shared__ __align__(16) float s_w[64 * 16];
    __shared__ float s_b[16];
    __shared__ __align__(16) float s_cb[512 * 16];
    __shared__ float s_cn[512];
    __shared__ float sred[32];

    for (int i = threadIdx.x; i < 1024; i += 256) {
        int d = i & 15, ic = i >> 4;
        s_w[i] = w3[d * 64 + ic];
    }
    if (threadIdx.x < 16) s_b[threadIdx.x] = b3[threadIdx.x];
    for (int i = threadIdx.x; i < 8192; i += 256) s_cb[i] = cb[i];
    __syncthreads();
    for (int j = threadIdx.x; j < 512; j += 256) {
        float s = 0.f;
        #pragma unroll
        for (int d = 0; d < 16; d++) { float c = s_cb[j * 16 + d]; s = fmaf(c, c, s); }
        s_cn[j] = s;
    }
    __syncthreads();

    int tid = blockIdx.x * 256 + threadIdx.x;
    int p = tid & 4095, b = tid >> 12;

    float z[16];
    #pragma unroll
    for (int d = 0; d < 16; d++) z[d] = s_b[d];
    const float* ap = g_a2 + (size_t)b * 64 * 4096 + p;
    #pragma unroll 8
    for (int ic = 0; ic < 64; ic++) {
        float v = ap[ic * 4096];
        const float4* wp = (const float4*)&s_w[ic * 16];
        #pragma unroll
        for (int j = 0; j < 4; j++) { float4 w4 = wp[j]; FMA4(z, j, v, w4); }
    }

    int best = 0; float bd = 3.4e38f;
    for (int j = 0; j < 512; j++) {
        const float4* cp = (const float4*)&s_cb[j * 16];
        float dot = 0.f;
        #pragma unroll
        for (int q4 = 0; q4 < 4; q4++) {
            float4 c4 = cp[q4];
            dot = fmaf(z[4*q4+0], c4.x, dot);
            dot = fmaf(z[4*q4+1], c4.y, dot);
            dot = fmaf(z[4*q4+2], c4.z, dot);
            dot = fmaf(z[4*q4+3], c4.w, dot);
        }
        float dist = s_cn[j] - 2.f * dot;
        if (dist < bd) { bd = dist; best = j; }
    }

    float sq = 0.f;
    float* qp = g_q + (size_t)b * 16 * 4096 + p;
    #pragma unroll
    for (int d = 0; d < 16; d++) {
        float qv = s_cb[best * 16 + d];
        float df = qv - z[d];
        sq = fmaf(df, df, sq);
        qp[d * 4096] = qv;
    }
    float bs = block_sum(sq, sred);
    if (threadIdx.x == 0) g_pvq[blockIdx.x] = bs;
}

// ---------------- dec1: convT 16->64 k3 s2 p1 op1, ReLU (oc-pair, RR=4) --------------
// block: chunk(16) x ocg(8) x r(2) = 256. grid: 64b * 2ph * 8rg = 1024.
__global__ void __launch_bounds__(256, 2) k_dec1(const float* __restrict__ w,
                                                 const float* __restrict__ bias) {
    extern __shared__ __align__(16) ull smu[];
    ull* s_w1 = smu;              // [kh][ic][32 ocp] 1536 each
    ull* s_w2 = smu + 1536;
    ull* s_w0 = smu + 3072;
    ull* s_bd = smu + 4608;       // 32
    for (int i = threadIdx.x; i < 1536; i += 256) {
        int ocp = i & 31, ic = (i >> 5) & 15, kh = i >> 9;
        const float* wa = w + ((ic * 64 + 2 * ocp) * 3 + kh) * 3;       // dec_w1 [16][64][3][3]
        const float* wb = w + ((ic * 64 + 2 * ocp + 1) * 3 + kh) * 3;
        s_w1[i] = pk2(wa[1], wb[1]);
        s_w2[i] = pk2(wa[2], wb[2]);
        s_w0[i] = pk2(wa[0], wb[0]);
    }
    if (threadIdx.x < 32) s_bd[threadIdx.x] = pk2(bias[2*threadIdx.x], bias[2*threadIdx.x+1]);
    __syncthreads();

    int tx = threadIdx.x;
    int chunk = tx & 15, ocg = (tx >> 4) & 7, r = tx >> 7;
    int bi = blockIdx.x;
    int b = bi >> 4, rem = bi & 15, ph = rem >> 3, rg = rem & 7;
    int ocp0 = ocg * 4;
    int ow0 = chunk * 8;
    const float* base = g_q + (size_t)b * 16 * 4096 + chunk * 4;
    bool edge = (chunk < 15);

    #pragma unroll 1
    for (int rr = 0; rr < 4; rr++) {
        int R = rg * 8 + rr * 2 + r;
        int oh = 2 * R + ph;

        ull ae[16], ao[16];
        #pragma unroll
        for (int p = 0; p < 4; p++) {
            ull bp = s_bd[ocp0 + p];
            ae[p] = bp; ae[4+p] = bp; ae[8+p] = bp; ae[12+p] = bp;
            ao[p] = bp; ao[4+p] = bp; ao[8+p] = bp; ao[12+p] = bp;
        }

        if (ph == 0) {             // single tap kh=1 @ row R
            const float* p0 = base + R * 64;
            #pragma unroll 1
            for (int ic = 0; ic < 16; ic += 4) {
                float4 f0 = *(const float4*)(p0 + (ic + 0) * 4096);
                float4 f1 = *(const float4*)(p0 + (ic + 1) * 4096);
                float4 f2 = *(const float4*)(p0 + (ic + 2) * 4096);
                float4 f3 = *(const float4*)(p0 + (ic + 3) * 4096);
                float v0 = __shfl_down_sync(FULLMASK, f0.x, 1); if (!edge) v0 = 0.f;
                float v1 = __shfl_down_sync(FULLMASK, f1.x, 1); if (!edge) v1 = 0.f;
                float v2 = __shfl_down_sync(FULLMASK, f2.x, 1); if (!edge) v2 = 0.f;
                float v3 = __shfl_down_sync(FULLMASK, f3.x, 1); if (!edge) v3 = 0.f;
                int t0 = (16 + ic) * 32 + ocp0;
                ptap(f0, v0, s_w1 + t0,      s_w2 + t0,      s_w0 + t0,      ae, ao);
                ptap(f1, v1, s_w1 + t0 + 32, s_w2 + t0 + 32, s_w0 + t0 + 32, ae, ao);
                ptap(f2, v2, s_w1 + t0 + 64, s_w2 + t0 + 64, s_w0 + t0 + 64, ae, ao);
                ptap(f3, v3, s_w1 + t0 + 96, s_w2 + t0 + 96, s_w0 + t0 + 96, ae, ao);
            }
        } else {                   // taps kh=2 @ R, kh=0 @ R+1
            bool ok = (R + 1 < 64);
            const float* pa = base + R * 64;
            const float* pb = base + (R + 1) * 64;
            #pragma unroll 1
            for (int ic = 0; ic < 16; ic += 2) {
                float4 fa0 = *(const float4*)(pa + ic * 4096);
                float4 fa1 = *(const float4*)(pa + (ic + 1) * 4096);
                float4 fb0 = ok ? *(const float4*)(pb + ic * 4096) : z4();
                float4 fb1 = ok ? *(const float4*)(pb + (ic + 1) * 4096) : z4();
                float va0 = __shfl_down_sync(FULLMASK, fa0.x, 1); if (!edge) va0 = 0.f;
                float va1 = __shfl_down_sync(FULLMASK, fa1.x, 1); if (!edge) va1 = 0.f;
                float vb0 = __shfl_down_sync(FULLMASK, fb0.x, 1); if (!edge) vb0 = 0.f;
                float vb1 = __shfl_down_sync(FULLMASK, fb1.x, 1); if (!edge) vb1 = 0.f;
                int ta = (32 + ic) * 32 + ocp0;   // kh=2
                int tb = ic * 32 + ocp0;          // kh=0
                ptap(fa0, va0, s_w1 + ta,      s_w2 + ta,      s_w0 + ta,      ae, ao);
                ptap(fb0, vb0, s_w1 + tb,      s_w2 + tb,      s_w0 + tb,      ae, ao);
                ptap(fa1, va1, s_w1 + ta + 32, s_w2 + ta + 32, s_w0 + ta + 32, ae, ao);
                ptap(fb1, vb1, s_w1 + tb + 32, s_w2 + tb + 32, s_w0 + tb + 32, ae, ao);
            }
        }

        float* op = g_d1 + ((size_t)(b * 64 + ocg * 8) * 128 + oh) * 128 + ow0;
        #pragma unroll
        for (int p = 0; p < 4; p++) {
            float2 e0 = upk2(ae[p]), e1 = upk2(ae[4+p]), e2 = upk2(ae[8+p]), e3 = upk2(ae[12+p]);
            float2 q0 = upk2(ao[p]), q1 = upk2(ao[4+p]), q2 = upk2(ao[8+p]), q3 = upk2(ao[12+p]);
            float* d0 = op + (size_t)(2*p) * 16384;
            float* d1 = d0 + 16384;
            *(float4*)d0       = make_float4(rl(e0.x), rl(q0.x), rl(e1.x), rl(q1.x));
            *(float4*)(d0 + 4) = make_float4(rl(e2.x), rl(q2.x), rl(e3.x), rl(q3.x));
            *(float4*)d1       = make_float4(rl(e0.y), rl(q0.y), rl(e1.y), rl(q1.y));
            *(float4*)(d1 + 4) = make_float4(rl(e2.y), rl(q2.y), rl(e3.y), rl(q3.y));
        }
    }
}

// ---------------- dec2: convT 64->32 k3 s2 p1 op1, ReLU (oc-pair, RR=4) --------------
// block: chunk(32) x ocg(4) x r(2) = 256. grid: 64b * 2ph * 16rg = 2048.
__global__ void __launch_bounds__(256, 2) k_dec2(const float* __restrict__ w,
                                                 const float* __restrict__ bias) {
    extern __shared__ __align__(16) ull smu[];
    ull* s_w1 = smu;              // [kh][ic][16 ocp] 3072 each
    ull* s_w2 = smu + 3072;
    ull* s_w0 = smu + 6144;
    ull* s_bd = smu + 9216;       // 16
    for (int i = threadIdx.x; i < 3072; i += 256) {
        int ocp = i & 15, ic = (i >> 4) & 63, kh = i >> 10;
        const float* wa = w + ((ic * 32 + 2 * ocp) * 3 + kh) * 3;       // dec_w2 [64][32][3][3]
        const float* wb = w + ((ic * 32 + 2 * ocp + 1) * 3 + kh) * 3;
        s_w1[i] = pk2(wa[1], wb[1]);
        s_w2[i] = pk2(wa[2], wb[2]);
        s_w0[i] = pk2(wa[0], wb[0]);
    }
    if (threadIdx.x < 16) s_bd[threadIdx.x] = pk2(bias[2*threadIdx.x], bias[2*threadIdx.x+1]);
    __syncthreads();

    int tx = threadIdx.x;
    int chunk = tx & 31, ocg = (tx >> 5) & 3, r = tx >> 7;
    int bi = blockIdx.x;
    int b = bi >> 5, rem = bi & 31, ph = rem >> 4, rg = rem & 15;
    int ocp0 = ocg * 4;
    int ow0 = chunk * 8;
    const float* base = g_d1 + (size_t)b * 64 * 16384 + chunk * 4;
    bool edge = (chunk < 31);

    #pragma unroll 1
    for (int rr = 0; rr < 4; rr++) {
        int R = rg * 8 + rr * 2 + r;
        int oh = 2 * R + ph;

        ull ae[16], ao[16];
        #pragma unroll
        for (int p = 0; p < 4; p++) {
            ull bp = s_bd[ocp0 + p];
            ae[p] = bp; ae[4+p] = bp; ae[8+p] = bp; ae[12+p] = bp;
            ao[p] = bp; ao[4+p] = bp; ao[8+p] = bp; ao[12+p] = bp;
        }

        if (ph == 0) {             // single tap kh=1 @ row R
            const float* p0 = base + R * 128;
            #pragma unroll 1
            for (int ic = 0; ic < 64; ic += 4) {
                float4 f0 = *(const float4*)(p0 + (size_t)(ic + 0) * 16384);
                float4 f1 = *(const float4*)(p0 + (size_t)(ic + 1) * 16384);
                float4 f2 = *(const float4*)(p0 + (size_t)(ic + 2) * 16384);
                float4 f3 = *(const float4*)(p0 + (size_t)(ic + 3) * 16384);
                float v0 = __shfl_down_sync(FULLMASK, f0.x, 1); if (!edge) v0 = 0.f;
                float v1 = __shfl_down_sync(FULLMASK, f1.x, 1); if (!edge) v1 = 0.f;
                float v2 = __shfl_down_sync(FULLMASK, f2.x, 1); if (!edge) v2 = 0.f;
                float v3 = __shfl_down_sync(FULLMASK, f3.x, 1); if (!edge) v3 = 0.f;
                int t0 = (64 + ic) * 16 + ocp0;
                ptap(f0, v0, s_w1 + t0,      s_w2 + t0,      s_w0 + t0,      ae, ao);
                ptap(f1, v1, s_w1 + t0 + 16, s_w2 + t0 + 16, s_w0 + t0 + 16, ae, ao);
                ptap(f2, v2, s_w1 + t0 + 32, s_w2 + t0 + 32, s_w0 + t0 + 32, ae, ao);
                ptap(f3, v3, s_w1 + t0 + 48, s_w2 + t0 + 48, s_w0 + t0 + 48, ae, ao);
            }
        } else {                   // taps kh=2 @ R, kh=0 @ R+1
            bool ok = (R + 1 < 128);
            const float* pa = base + R * 128;
            const float* pb = base + (R + 1) * 128;
            #pragma unroll 1
            for (int ic = 0; ic < 64; ic += 2) {
                float4 fa0 = *(const float4*)(pa + (size_t)ic * 16384);
                float4 fa1 = *(const float4*)(pa + (size_t)(ic + 1) * 16384);
                float4 fb0 = ok ? *(const float4*)(pb + (size_t)ic * 16384) : z4();
                float4 fb1 = ok ? *(const float4*)(pb + (size_t)(ic + 1) * 16384) : z4();
                float va0 = __shfl_down_sync(FULLMASK, fa0.x, 1); if (!edge) va0 = 0.f;
                float va1 = __shfl_down_sync(FULLMASK, fa1.x, 1); if (!edge) va1 = 0.f;
                float vb0 = __shfl_down_sync(FULLMASK, fb0.x, 1); if (!edge) vb0 = 0.f;
                float vb1 = __shfl_down_sync(FULLMASK, fb1.x, 1); if (!edge) vb1 = 0.f;
                int ta = (128 + ic) * 16 + ocp0;   // kh=2
                int tb = ic * 16 + ocp0;           // kh=0
                ptap(fa0, va0, s_w1 + ta,      s_w2 + ta,      s_w0 + ta,      ae, ao);
                ptap(fb0, vb0, s_w1 + tb,      s_w2 + tb,      s_w0 + tb,      ae, ao);
                ptap(fa1, va1, s_w1 + ta + 16, s_w2 + ta + 16, s_w0 + ta + 16, ae, ao);
                ptap(fb1, vb1, s_w1 + tb + 16, s_w2 + tb + 16, s_w0 + tb + 16, ae, ao);
            }
        }

        float* op = g_d2 + ((size_t)(b * 32 + ocg * 8) * 256 + oh) * 256 + ow0;
        #pragma unroll
        for (int p = 0; p < 4; p++) {
            float2 e0 = upk2(ae[p]), e1 = upk2(ae[4+p]), e2 = upk2(ae[8+p]), e3 = upk2(ae[12+p]);
            float2 q0 = upk2(ao[p]), q1 = upk2(ao[4+p]), q2 = upk2(ao[8+p]), q3 = upk2(ao[12+p]);
            float* d0 = op + (size_t)(2*p) * 65536;
            float* d1 = d0 + 65536;
            *(float4*)d0       = make_float4(rl(e0.x), rl(q0.x), rl(e1.x), rl(q1.x));
            *(float4*)(d0 + 4) = make_float4(rl(e2.x), rl(q2.x), rl(e3.x), rl(q3.x));
            *(float4*)d1       = make_float4(rl(e0.y), rl(q0.y), rl(e1.y), rl(q1.y));
            *(float4*)(d1 + 4) = make_float4(rl(e2.y), rl(q2.y), rl(e3.y), rl(q3.y));
        }
    }
}

// ---------------- dec3: convT 32->3 s1 p1 + fused MSE (unchanged from R10) -----------
__global__ void __launch_bounds__(256) k_dec3_mse(const float* __restrict__ w,
                                                  const float* __restrict__ bias,
                                                  const float* __restrict__ x) {
    __shared__ __align__(16) ull s_wd[864];   // [ic][kh][kw][oc] dup pairs
    __shared__ ull s_bd[3];
    __shared__ float sred[32];
    for (int i = threadIdx.x; i < 864; i += 256) {
        int oc = i % 3; int t = i / 3; int kw = t % 3; t /= 3; int kh = t % 3; int ic = t / 3;
        float wv = w[ic * 27 + oc * 9 + (2 - kh) * 3 + (2 - kw)];   // dec_w3 flipped
        s_wd[i] = pk2(wv, wv);
    }
    if (threadIdx.x < 3) { float bv = bias[threadIdx.x]; s_bd[threadIdx.x] = pk2(bv, bv); }
    __syncthreads();

    int tx = threadIdx.x;
    int chunk = tx & 31, r = tx >> 5;
    int b = blockIdx.x >> 5, rg = blockIdx.x & 31;
    int oh = rg * 8 + r;
    int ow0 = chunk * 8;

    bool ok0 = (oh > 0), ok2 = (oh < 255);
    bool eL = (chunk != 0), eR = (chunk != 31);

    ull acc[12];
    #pragma unroll
    for (int oc = 0; oc < 3; oc++) {
        ull bp = s_bd[oc];
        acc[oc*4+0] = bp; acc[oc*4+1] = bp; acc[oc*4+2] = bp; acc[oc*4+3] = bp;
    }

    #pragma unroll 1
    for (int ic = 0; ic < 32; ic++) {
        const float* rowm = g_d2 + (size_t)(b * 32 + ic) * 65536 + (oh - 1) * 256 + ow0;
        float4 m0 = ok0 ? *(const float4*)rowm       : z4();
        float4 m1 = ok0 ? *(const float4*)(rowm + 4) : z4();
        float4 c0 = *(const float4*)(rowm + 256);
        float4 c1 = *(const float4*)(rowm + 260);
        float4 b0 = ok2 ? *(const float4*)(rowm + 512) : z4();
        float4 b1 = ok2 ? *(const float4*)(rowm + 516) : z4();
        float mm1 = __shfl_up_sync(FULLMASK, m1.w, 1);   if (!eL) mm1 = 0.f;
        float cm1 = __shfl_up_sync(FULLMASK, c1.w, 1);   if (!eL) cm1 = 0.f;
        float bm1 = __shfl_up_sync(FULLMASK, b1.w, 1);   if (!eL) bm1 = 0.f;
        float m8  = __shfl_down_sync(FULLMASK, m0.x, 1); if (!eR) m8 = 0.f;
        float c8  = __shfl_down_sync(FULLMASK, c0.x, 1); if (!eR) c8 = 0.f;
        float b8  = __shfl_down_sync(FULLMASK, b0.x, 1); if (!eR) b8 = 0.f;

        const ull* wp = s_wd + ic * 27;   // [kh][kw][oc]
        #pragma unroll
        for (int kh = 0; kh < 3; kh++) {
            float4 f0 = (kh == 0) ? m0 : (kh == 1) ? c0 : b0;
            float4 f1 = (kh == 0) ? m1 : (kh == 1) ? c1 : b1;
            float vm1 = (kh == 0) ? mm1 : (kh == 1) ? cm1 : bm1;
            float v8  = (kh == 0) ? m8  : (kh == 1) ? c8  : b8;
            ull A0 = pk2(f0.x, f0.y), A1 = pk2(f0.z, f0.w), A2 = pk2(f1.x, f1.y), A3 = pk2(f1.z, f1.w);
            ull O0 = pk2(vm1, f0.x), O1 = pk2(f0.y, f0.z), O2 = pk2(f0.w, f1.x),
                O3 = pk2(f1.y, f1.z), O4 = pk2(f1.w, v8);
            const ull* wk = wp + kh * 9;
            #pragma unroll
            for (int oc = 0; oc < 3; oc++) {
                ull w0 = wk[oc], w1 = wk[3 + oc], w2 = wk[6 + oc];
                acc[oc*4+0] = ffma2(O0, w0, ffma2(A0, w1, ffma2(O1, w2, acc[oc*4+0])));
                acc[oc*4+1] = ffma2(O1, w0, ffma2(A1, w1, ffma2(O2, w2, acc[oc*4+1])));
                acc[oc*4+2] = ffma2(O2, w0, ffma2(A2, w1, ffma2(O3, w2, acc[oc*4+2])));
                acc[oc*4+3] = ffma2(O3, w0, ffma2(A3, w1, ffma2(O4, w2, acc[oc*4+3])));
            }
        }
    }

    const float* xp = x + (size_t)b * 3 * 65536 + oh * 256 + ow0;
    float sq = 0.f;
    #pragma unroll
    for (int oc = 0; oc < 3; oc++) {
        float4 x0 = *(const float4*)(xp + (size_t)oc * 65536);
        float4 x1 = *(const float4*)(xp + (size_t)oc * 65536 + 4);
        float2 p0 = upk2(acc[oc*4+0]), p1 = upk2(acc[oc*4+1]);
        float2 p2 = upk2(acc[oc*4+2]), p3 = upk2(acc[oc*4+3]);
        float e;
        e = p0.x - x0.x; sq = fmaf(e, e, sq);
        e = p0.y - x0.y; sq = fmaf(e, e, sq);
        e = p1.x - x0.z; sq = fmaf(e, e, sq);
        e = p1.y - x0.w; sq = fmaf(e, e, sq);
        e = p2.x - x1.x; sq = fmaf(e, e, sq);
        e = p2.y - x1.y; sq = fmaf(e, e, sq);
        e = p3.x - x1.z; sq = fmaf(e, e, sq);
        e = p3.y - x1.w; sq = fmaf(e, e, sq);
    }
    float bs = block_sum(sq, sred);
    if (threadIdx.x == 0) g_pmse[blockIdx.x] = bs;
}

// ---------------- deterministic final reduction ----------------
__global__ void k_final(float* __restrict__ out) {
    __shared__ double sd[256];
    double s1 = 0.0, s2 = 0.0;
    for (int i = threadIdx.x; i < 1024; i += 256) s1 += (double)g_pvq[i];
    for (int i = threadIdx.x; i < 2048; i += 256) s2 += (double)g_pmse[i];
    sd[threadIdx.x] = s1; __syncthreads();
    for (int o = 128; o > 0; o >>= 1) {
        if ((int)threadIdx.x < o) sd[threadIdx.x] += sd[threadIdx.x + o];
        __syncthreads();
    }
    double vq = sd[0]; __syncthreads();
    sd[threadIdx.x] = s2; __syncthreads();
    for (int o = 128; o > 0; o >>= 1) {
        if ((int)threadIdx.x < o) sd[threadIdx.x] += sd[threadIdx.x + o];
        __syncthreads();
    }
    if (threadIdx.x == 0) {
        double mq = vq / 4194304.0;                 // 64*64*64*16
        double mr = sd[0] / 12582912.0;             // 64*3*256*256
        out[0] = (float)(1.25 * mq);
        out[1] = (float)mr;
        out[2] = (float)mr;
    }
}

// ---------------- launch ----------------
extern "C" void kernel_launch(void* const* d_in, const int* in_sizes, int n_in,
                              void* d_out, int out_size) {
    const float* x   = (const float*)d_in[0];
    const float* ew1 = (const float*)d_in[1];
    const float* eb1 = (const float*)d_in[2];
    const float* ew2 = (const float*)d_in[3];
    const float* eb2 = (const float*)d_in[4];
    const float* ew3 = (const float*)d_in[5];
    const float* eb3 = (const float*)d_in[6];
    const float* cb  = (const float*)d_in[7];
    const float* dw1 = (const float*)d_in[8];
    const float* db1 = (const float*)d_in[9];
    const float* dw2 = (const float*)d_in[10];
    const float* db2 = (const float*)d_in[11];
    const float* dw3 = (const float*)d_in[12];
    const float* db3 = (const float*)d_in[13];
    float* out = (float*)d_out;

    const int smem_enc2 = (9216 + 32) * 8;   // 73984 B
    const int smem_dec1 = (4608 + 32) * 8;   // 37120 B
    const int smem_dec2 = (9216 + 16) * 8;   // 73856 B
    cudaFuncSetAttribute(k_enc2, cudaFuncAttributeMaxDynamicSharedMemorySize, smem_enc2);
    cudaFuncSetAttribute(k_dec1, cudaFuncAttributeMaxDynamicSharedMemorySize, smem_dec1);
    cudaFuncSetAttribute(k_dec2, cudaFuncAttributeMaxDynamicSharedMemorySize, smem_dec2);

    k_enc1    <<<2048, 256>>>(x, ew1, eb1);
    k_enc2    <<<512, 256, smem_enc2>>>(ew2, eb2);
    k_enc3_vq <<<1024, 256>>>(ew3, eb3, cb);
    k_dec1    <<<1024, 256, smem_dec1>>>(dw1, db1);
    k_dec2    <<<2048, 256, smem_dec2>>>(dw2, db2);
    k_dec3_mse<<<2048, 256>>>(dw3, db3, x);
    k_final   <<<1, 256>>>(out);
}